// round 10
// baseline (speedup 1.0000x reference)
#include <cuda_runtime.h>
#include <cuda_bf16.h>
#include <math.h>
#include <stdint.h>

#define MAXN 100000
#define MAXE 800000
#define FD 64
#define BN_EPS 1e-5f

typedef unsigned long long ULL;

// ---------------- scratch (no allocations allowed) ----------------
__device__ int   g_cnt[MAXN];
__device__ int   g_off[MAXN + 1];
__device__ int   g_cursor[MAXN];
__device__ int   g_bsum[512];
__device__ float g_dis[MAXN];
__device__ ULL   g_csr[MAXE];     // packed {src:int, norm:float}
__device__ float g_H[(size_t)MAXN * FD];
__device__ float g_G[(size_t)MAXN * FD];
__device__ float g_Wm[FD * FD];   // W3 @ pW1 fp32
// W bf16 hi/lo planes, layout [k][72] bf16 (=576 uint4), slots: 0=W1,1=W2,2=Wm,3=pW2
__device__ uint4 g_wpH[4][576];
__device__ uint4 g_wpL[4][576];
__device__ float g_scale1[FD], g_shift1[FD];
__device__ float g_scale2[FD], g_shift2[FD];
__device__ float g_fb[FD];
__device__ int   g_is64;

// ---------------- init: zero counts + edge dtype detect ----------------
__global__ void k_init(const unsigned int* ei, int n) {
    int i = blockIdx.x * blockDim.x + threadIdx.x;
    if (i < n) g_cnt[i] = 0;
    if (i == 0) {
        int is64 = 1;
        for (int j = 1; j < 64; j += 2)
            if (ei[j] != 0u) { is64 = 0; break; }
        g_is64 = is64;
    }
}

__device__ __forceinline__ int load_idx(const void* ei, long long pos) {
    if (g_is64) return (int)((const long long*)ei)[pos];
    return ((const int*)ei)[pos];
}

__global__ void k_count(const void* ei, int E) {
    int e = blockIdx.x * blockDim.x + threadIdx.x;
    if (e >= E) return;
    int dst = load_idx(ei, (long long)E + e);
    atomicAdd(&g_cnt[dst], 1);
}

// ---------------- helpers ----------------
__device__ __forceinline__ uint32_t packbf(float a, float b) {
    uint32_t r;
    asm("cvt.rn.bf16x2.f32 %0, %1, %2;" : "=r"(r) : "f"(b), "f"(a));  // lo=a, hi=b
    return r;
}
__device__ __forceinline__ float bfhi(float v) {
    return __bfloat162float(__float2bfloat16(v));
}

// Wm = W3 @ pW1 (fp32, one block)
__global__ void k_mm64(const float* __restrict__ A, const float* __restrict__ B,
                       float* __restrict__ C) {
    __shared__ float Bs[FD * FD];
    int tid = threadIdx.x;
#pragma unroll
    for (int i = 0; i < 16; i++) Bs[tid + i * 256] = B[tid + i * 256];
    __syncthreads();
    int r = tid >> 2, c0 = (tid & 3) * 16;
    float acc[16];
#pragma unroll
    for (int j = 0; j < 16; j++) acc[j] = 0.f;
    for (int k = 0; k < FD; k++) {
        float a = A[r * FD + k];
#pragma unroll
        for (int j = 0; j < 16; j++) acc[j] = fmaf(a, Bs[k * FD + c0 + j], acc[j]);
    }
#pragma unroll
    for (int j = 0; j < 16; j++) C[r * FD + c0 + j] = acc[j];
}

// split W into bf16 hi/lo planes, layout [k][72] bf16
__global__ void k_wsplit(const float* W1, const float* W2, const float* pW2) {
    int slot = blockIdx.x;
    const float* src = (slot == 0) ? W1 : (slot == 1) ? W2
                     : (slot == 2) ? g_Wm : pW2;
    __nv_bfloat16* ph = (__nv_bfloat16*)&g_wpH[slot][0];
    __nv_bfloat16* pl = (__nv_bfloat16*)&g_wpL[slot][0];
    int tid = threadIdx.x;
#pragma unroll
    for (int i = 0; i < 16; i++) {
        int e = tid + i * 256;          // 0..4095
        int k = e >> 6, nn = e & 63;
        float v = src[e];
        float h = bfhi(v);
        ph[k * 72 + nn] = __float2bfloat16(h);
        pl[k * 72 + nn] = __float2bfloat16(v - h);
    }
}

// ---------------- constants: BN folds + fused predictor bias ----------------
__global__ void k_consts(const float* b1, const float* g1, const float* bb1,
                         const float* m1, const float* v1,
                         const float* b2, const float* g2, const float* bb2,
                         const float* m2, const float* v2,
                         const float* b3, const float* pW1, const float* pb1) {
    int c = threadIdx.x;
    if (c >= FD) return;
    if (blockIdx.x == 0) {
        float s = g1[c] * rsqrtf(v1[c] + BN_EPS);
        g_scale1[c] = s;
        g_shift1[c] = (b1[c] - m1[c]) * s + bb1[c];
    } else if (blockIdx.x == 1) {
        float s = g2[c] * rsqrtf(v2[c] + BN_EPS);
        g_scale2[c] = s;
        g_shift2[c] = (b2[c] - m2[c]) * s + bb2[c];
    } else {
        float s = pb1[c];
        for (int k = 0; k < FD; k++) s += b3[k] * pW1[k * FD + c];
        g_fb[c] = s;
    }
}

// ---------------- scans ----------------
__global__ void k_scan1(int n) {
    __shared__ int s[256];
    int i = blockIdx.x * 256 + threadIdx.x;
    int v = (i < n) ? g_cnt[i] : 0;
    if (i < n) g_dis[i] = rsqrtf((float)(v + 1));   // +1 self loop
    s[threadIdx.x] = v;
    __syncthreads();
#pragma unroll
    for (int off = 1; off < 256; off <<= 1) {
        int t = (threadIdx.x >= off) ? s[threadIdx.x - off] : 0;
        __syncthreads();
        s[threadIdx.x] += t;
        __syncthreads();
    }
    if (i < n) g_off[i + 1] = s[threadIdx.x];
    if (threadIdx.x == 255) g_bsum[blockIdx.x] = s[255];
}

__global__ void k_scan2(int nb) {
    __shared__ int s[512];
    int t = threadIdx.x;
    int v = (t < nb) ? g_bsum[t] : 0;
    s[t] = v;
    __syncthreads();
#pragma unroll
    for (int off = 1; off < 512; off <<= 1) {
        int u = (t >= off) ? s[t - off] : 0;
        __syncthreads();
        s[t] += u;
        __syncthreads();
    }
    if (t < nb) g_bsum[t] = s[t] - v;   // exclusive
}

__global__ void k_scan3(int n) {
    int i = blockIdx.x * blockDim.x + threadIdx.x;
    if (i < n) {
        int off = g_off[i + 1] + g_bsum[i >> 8];
        g_off[i + 1] = off;
        g_cursor[i] = off - g_cnt[i];
    }
    if (i == 0) g_off[0] = 0;
}

__global__ void k_fill(const void* ei, int E) {
    int e = blockIdx.x * blockDim.x + threadIdx.x;
    if (e >= E) return;
    int s = load_idx(ei, e);
    int d = load_idx(ei, (long long)E + e);
    float norm = g_dis[s] * g_dis[d];
    int pos = atomicAdd(&g_cursor[d], 1);
    g_csr[pos] = (ULL)(unsigned int)s | ((ULL)__float_as_uint(norm) << 32);
}

// ================= fused layer: Y = EPI( (Â X) @ W )  (AGG=1) ==================
//                or Y = EPI( X @ W )                   (AGG=0)
// 128-row tile / block, 256 threads (8 warps). A operand built in smem as split
// bf16 (hi+lo); W hi/lo planes copied from global (prestaged, layout [k][72]).
// D = AhWh + AhWl + AlWh fp32 via mma.m16n8k16.
// EPI: 0=none, 1=BN1+ReLU, 2=BN2+ReLU, 3=tanh(.+fb), 4=+bias

#define LDA 72
#define ALO_OFF (128 * LDA * 2)            // 18432
#define WH_OFF  (2 * 128 * LDA * 2)        // 36864
#define WPLANE  (64 * LDA * 2)             // 9216
#define WL_OFF  (WH_OFF + WPLANE)
#define FS_SMEM (WH_OFF + 2 * WPLANE)      // 55296

__device__ __forceinline__ uint32_t smem_u32(const void* p) {
    uint32_t a;
    asm("{ .reg .u64 t; cvta.to.shared.u64 t, %1; cvt.u32.u64 %0, t; }"
        : "=r"(a) : "l"(p));
    return a;
}
__device__ __forceinline__ void ldmA(uint32_t addr, uint32_t r[4]) {
    asm volatile("ldmatrix.sync.aligned.m8n8.x4.shared.b16 {%0,%1,%2,%3}, [%4];"
                 : "=r"(r[0]), "=r"(r[1]), "=r"(r[2]), "=r"(r[3]) : "r"(addr));
}
__device__ __forceinline__ void ldmBT(uint32_t addr, uint32_t r[4]) {
    asm volatile("ldmatrix.sync.aligned.m8n8.x4.trans.shared.b16 {%0,%1,%2,%3}, [%4];"
                 : "=r"(r[0]), "=r"(r[1]), "=r"(r[2]), "=r"(r[3]) : "r"(addr));
}
__device__ __forceinline__ void hmma(float d[4], const uint32_t a[4],
                                     uint32_t b0, uint32_t b1) {
    asm volatile(
        "mma.sync.aligned.m16n8k16.row.col.f32.bf16.bf16.f32 "
        "{%0,%1,%2,%3}, {%4,%5,%6,%7}, {%8,%9}, {%0,%1,%2,%3};"
        : "+f"(d[0]), "+f"(d[1]), "+f"(d[2]), "+f"(d[3])
        : "r"(a[0]), "r"(a[1]), "r"(a[2]), "r"(a[3]), "r"(b0), "r"(b1));
}

template <int EPI, int AGG>
__global__ void __launch_bounds__(256)
k_fused(const float* __restrict__ X,
        const uint4* __restrict__ whp, const uint4* __restrict__ wlp,
        const float* __restrict__ bias, float* __restrict__ Y, int n) {
    extern __shared__ char smem[];
    uint32_t sb = smem_u32(smem);
    int tid = threadIdx.x, w = tid >> 5, lane = tid & 31;
    int row0 = blockIdx.x * 128;

    // copy W planes (576 uint4 each)
#pragma unroll
    for (int i = 0; i < 3; i++) {
        int idx = tid + i * 256;
        if (idx < 576) {
            ((uint4*)(smem + WH_OFF))[idx] = whp[idx];
            ((uint4*)(smem + WL_OFF))[idx] = wlp[idx];
        }
    }

    if (AGG) {
        // ---- phase 1: gather 16 nodes per warp, write split-bf16 A rows ----
        const float2* hp = (const float2*)X;
        for (int rl = 0; rl < 16; rl++) {
            int r = w * 16 + rl;
            int node = row0 + r;
            uint32_t hiw = 0u, low = 0u;
            if (node < n) {
                float d = g_dis[node];
                float2 acc = hp[(size_t)node * 32 + lane];
                float s2 = d * d;
                acc.x *= s2; acc.y *= s2;
                int e = g_off[node], end = g_off[node + 1];
                for (; e + 4 <= end; e += 4) {
                    ULL e0 = g_csr[e + 0];
                    ULL e1 = g_csr[e + 1];
                    ULL e2 = g_csr[e + 2];
                    ULL e3 = g_csr[e + 3];
                    float2 v0 = hp[(size_t)(unsigned)e0 * 32 + lane];
                    float2 v1 = hp[(size_t)(unsigned)e1 * 32 + lane];
                    float2 v2 = hp[(size_t)(unsigned)e2 * 32 + lane];
                    float2 v3 = hp[(size_t)(unsigned)e3 * 32 + lane];
                    float n0 = __uint_as_float((unsigned)(e0 >> 32));
                    float n1 = __uint_as_float((unsigned)(e1 >> 32));
                    float n2 = __uint_as_float((unsigned)(e2 >> 32));
                    float n3 = __uint_as_float((unsigned)(e3 >> 32));
                    acc.x = fmaf(v0.x, n0, acc.x); acc.y = fmaf(v0.y, n0, acc.y);
                    acc.x = fmaf(v1.x, n1, acc.x); acc.y = fmaf(v1.y, n1, acc.y);
                    acc.x = fmaf(v2.x, n2, acc.x); acc.y = fmaf(v2.y, n2, acc.y);
                    acc.x = fmaf(v3.x, n3, acc.x); acc.y = fmaf(v3.y, n3, acc.y);
                }
                for (; e < end; e++) {
                    ULL e0 = g_csr[e];
                    float2 v0 = hp[(size_t)(unsigned)e0 * 32 + lane];
                    float n0 = __uint_as_float((unsigned)(e0 >> 32));
                    acc.x = fmaf(v0.x, n0, acc.x); acc.y = fmaf(v0.y, n0, acc.y);
                }
                float h0 = bfhi(acc.x), h1 = bfhi(acc.y);
                hiw = packbf(h0, h1);
                low = packbf(acc.x - h0, acc.y - h1);
            }
            *(uint32_t*)(smem + r * (LDA * 2) + lane * 4) = hiw;
            *(uint32_t*)(smem + ALO_OFF + r * (LDA * 2) + lane * 4) = low;
        }
    } else {
        // ---- phase 1: plain X load + split ----
#pragma unroll
        for (int i = 0; i < 4; i++) {
            int t = tid + i * 256;
            int r = t >> 3, g = t & 7;
            int row = row0 + r;
            float4 a = make_float4(0.f, 0.f, 0.f, 0.f), b = a;
            if (row < n) {
                const float4* xp = (const float4*)(X + (size_t)row * FD + g * 8);
                a = xp[0]; b = xp[1];
            }
            float f[8] = {a.x, a.y, a.z, a.w, b.x, b.y, b.z, b.w};
            uint32_t hi[4], lo[4];
#pragma unroll
            for (int p = 0; p < 4; p++) {
                float h0 = bfhi(f[2 * p]), h1 = bfhi(f[2 * p + 1]);
                hi[p] = packbf(h0, h1);
                lo[p] = packbf(f[2 * p] - h0, f[2 * p + 1] - h1);
            }
            int off = r * (LDA * 2) + g * 16;
            *(uint4*)(smem + off) = make_uint4(hi[0], hi[1], hi[2], hi[3]);
            *(uint4*)(smem + ALO_OFF + off) = make_uint4(lo[0], lo[1], lo[2], lo[3]);
        }
    }
    __syncthreads();

    // ---- phase 2: HMMA mainloop (round-8 layout) ----
    uint32_t aA = sb + ((w * 16 + (lane & 15)) * LDA + (lane >> 4) * 8) * 2;
    uint32_t aAl = aA + ALO_OFF;
    uint32_t aB = sb + WH_OFF + ((lane & 15) * LDA + (lane >> 4) * 8) * 2;
    uint32_t aBl = aB + WPLANE;

    float acc[8][4];
#pragma unroll
    for (int i = 0; i < 8; i++)
#pragma unroll
        for (int j = 0; j < 4; j++) acc[i][j] = 0.f;

#pragma unroll
    for (int ks = 0; ks < 4; ks++) {
        uint32_t ah[4], al[4];
        ldmA(aA + ks * 32, ah);
        ldmA(aAl + ks * 32, al);
        uint32_t krow = ks * 16 * LDA * 2;
#pragma unroll
        for (int pr = 0; pr < 4; pr++) {
            uint32_t bh[4], bl[4];
            ldmBT(aB + krow + pr * 32, bh);
            ldmBT(aBl + krow + pr * 32, bl);
            int nt = pr * 2;
            hmma(acc[nt],     ah, bh[0], bh[1]);
            hmma(acc[nt],     ah, bl[0], bl[1]);
            hmma(acc[nt],     al, bh[0], bh[1]);
            hmma(acc[nt + 1], ah, bh[2], bh[3]);
            hmma(acc[nt + 1], ah, bl[2], bl[3]);
            hmma(acc[nt + 1], al, bh[2], bh[3]);
        }
    }

    // ---- epilogue ----
    int r0 = row0 + w * 16 + (lane >> 2);
    int cbase = (lane & 3) * 2;
#pragma unroll
    for (int half = 0; half < 2; half++) {
        int row = r0 + half * 8;
        if (row >= n) continue;
        float* yr = Y + (size_t)row * FD;
#pragma unroll
        for (int nt = 0; nt < 8; nt++) {
            int c = nt * 8 + cbase;
            float2 v = make_float2(acc[nt][2 * half], acc[nt][2 * half + 1]);
            if (EPI == 1) {
                v.x = fmaxf(fmaf(v.x, g_scale1[c],     g_shift1[c]),     0.f);
                v.y = fmaxf(fmaf(v.y, g_scale1[c + 1], g_shift1[c + 1]), 0.f);
            } else if (EPI == 2) {
                v.x = fmaxf(fmaf(v.x, g_scale2[c],     g_shift2[c]),     0.f);
                v.y = fmaxf(fmaf(v.y, g_scale2[c + 1], g_shift2[c + 1]), 0.f);
            } else if (EPI == 3) {
                v.x = tanhf(v.x + g_fb[c]);
                v.y = tanhf(v.y + g_fb[c + 1]);
            } else if (EPI == 4) {
                v.x += bias[c];
                v.y += bias[c + 1];
            }
            *(float2*)(yr + c) = v;
        }
    }
}

// ---------------- launch ----------------
extern "C" void kernel_launch(void* const* d_in, const int* in_sizes, int n_in,
                              void* d_out, int out_size) {
    const float* x    = (const float*)d_in[0];
    const void*  ei   = d_in[1];
    const float* W1   = (const float*)d_in[2];
    const float* b1   = (const float*)d_in[3];
    const float* W2   = (const float*)d_in[4];
    const float* b2   = (const float*)d_in[5];
    const float* W3   = (const float*)d_in[6];
    const float* b3   = (const float*)d_in[7];
    const float* bn1g = (const float*)d_in[8];
    const float* bn1b = (const float*)d_in[9];
    const float* bn1m = (const float*)d_in[10];
    const float* bn1v = (const float*)d_in[11];
    const float* bn2g = (const float*)d_in[12];
    const float* bn2b = (const float*)d_in[13];
    const float* bn2m = (const float*)d_in[14];
    const float* bn2v = (const float*)d_in[15];
    const float* pW1  = (const float*)d_in[16];
    const float* pb1  = (const float*)d_in[17];
    const float* pW2  = (const float*)d_in[18];
    const float* pb2  = (const float*)d_in[19];
    float* out = (float*)d_out;

    int n = in_sizes[0] / FD;
    int E = in_sizes[1] / 2;
    if (n > MAXN) n = MAXN;
    if (E > MAXE) E = MAXE;

    float *H, *G, *WM;
    uint4 *WPH, *WPL;
    cudaGetSymbolAddress((void**)&H,   g_H);
    cudaGetSymbolAddress((void**)&G,   g_G);
    cudaGetSymbolAddress((void**)&WM,  g_Wm);
    cudaGetSymbolAddress((void**)&WPH, g_wpH);
    cudaGetSymbolAddress((void**)&WPL, g_wpL);

    cudaFuncSetAttribute(k_fused<1,1>, cudaFuncAttributeMaxDynamicSharedMemorySize, FS_SMEM);
    cudaFuncSetAttribute(k_fused<2,1>, cudaFuncAttributeMaxDynamicSharedMemorySize, FS_SMEM);
    cudaFuncSetAttribute(k_fused<3,1>, cudaFuncAttributeMaxDynamicSharedMemorySize, FS_SMEM);
    cudaFuncSetAttribute(k_fused<4,0>, cudaFuncAttributeMaxDynamicSharedMemorySize, FS_SMEM);

    const int TB = 256;
    int gb_n   = (n + TB - 1) / TB;
    int gb_e   = (E + TB - 1) / TB;
    int ntiles = (n + 127) / 128;         // 128-row tiles
    int nb     = (n + 255) / 256;         // scan blocks

    // setup: CSR + weights + constants
    k_init<<<gb_n, TB>>>((const unsigned int*)ei, n);
    k_count<<<gb_e, TB>>>(ei, E);
    k_mm64<<<1, TB>>>(W3, pW1, WM);
    k_wsplit<<<4, TB>>>(W1, W2, pW2);
    k_consts<<<3, FD>>>(b1, bn1g, bn1b, bn1m, bn1v,
                        b2, bn2g, bn2b, bn2m, bn2v,
                        b3, pW1, pb1);
    k_scan1<<<nb, 256>>>(n);
    k_scan2<<<1, 512>>>(nb);
    k_scan3<<<gb_n, TB>>>(n);
    k_fill<<<gb_e, TB>>>(ei, E);

    // layer 1: G = relu(BN1( (Â x) @ W1 ))     [b1 folded into shift1]
    k_fused<1,1><<<ntiles, TB, FS_SMEM>>>(x, WPH + 0, WPL + 0, nullptr, G, n);
    // layer 2: H = relu(BN2( (Â G) @ W2 ))
    k_fused<2,1><<<ntiles, TB, FS_SMEM>>>(G, WPH + 576, WPL + 576, nullptr, H, n);
    // layer 3 + predictor-1: G = tanh( (Â H) @ Wm + fb )
    k_fused<3,1><<<ntiles, TB, FS_SMEM>>>(H, WPH + 1152, WPL + 1152, nullptr, G, n);
    // predictor output: out = G @ pW2 + pb2
    k_fused<4,0><<<ntiles, TB, FS_SMEM>>>(G, WPH + 1728, WPL + 1728, pb2, out, n);
}

// round 11
// speedup vs baseline: 1.3171x; 1.3171x over previous
#include <cuda_runtime.h>
#include <cuda_bf16.h>
#include <math.h>
#include <stdint.h>

#define MAXN 100000
#define MAXE 800000
#define FD 64
#define BN_EPS 1e-5f

typedef unsigned long long ULL;

// ---------------- scratch (no allocations allowed) ----------------
__device__ int   g_cnt[MAXN];
__device__ int   g_off[MAXN + 1];
__device__ int   g_cursor[MAXN];
__device__ int   g_bsum[512];
__device__ float g_dis[MAXN];
__device__ ULL   g_csr[MAXE];     // packed {src:int, norm:float}
__device__ float g_H[(size_t)MAXN * FD];
__device__ float g_G[(size_t)MAXN * FD];
__device__ float g_Wm[FD * FD];   // W3 @ pW1 fp32
// W bf16 hi/lo planes, layout [k][72] bf16 (=576 uint4); slots 0=W1,1=W2,2=Wm,3=pW2
__device__ uint4 g_wpH[4][576];
__device__ uint4 g_wpL[4][576];
__device__ float g_scale1[FD], g_shift1[FD];
__device__ float g_scale2[FD], g_shift2[FD];
__device__ float g_fb[FD];
__device__ int   g_is64;

// ---------------- init: zero counts + edge dtype detect ----------------
__global__ void k_init(const unsigned int* ei, int n) {
    int i = blockIdx.x * blockDim.x + threadIdx.x;
    if (i < n) g_cnt[i] = 0;
    if (i == 0) {
        int is64 = 1;
        for (int j = 1; j < 64; j += 2)
            if (ei[j] != 0u) { is64 = 0; break; }
        g_is64 = is64;
    }
}

__device__ __forceinline__ int load_idx(const void* ei, long long pos) {
    if (g_is64) return (int)((const long long*)ei)[pos];
    return ((const int*)ei)[pos];
}

__global__ void k_count(const void* ei, int E) {
    int e = blockIdx.x * blockDim.x + threadIdx.x;
    if (e >= E) return;
    int dst = load_idx(ei, (long long)E + e);
    atomicAdd(&g_cnt[dst], 1);
}

// ---------------- helpers ----------------
__device__ __forceinline__ uint32_t packbf(float a, float b) {
    uint32_t r;
    asm("cvt.rn.bf16x2.f32 %0, %1, %2;" : "=r"(r) : "f"(b), "f"(a));  // lo=a, hi=b
    return r;
}
__device__ __forceinline__ float bfhi(float v) {
    return __bfloat162float(__float2bfloat16(v));
}

// Wm = W3 @ pW1 (fp32, one block)
__global__ void k_mm64(const float* __restrict__ A, const float* __restrict__ B,
                       float* __restrict__ C) {
    __shared__ float Bs[FD * FD];
    int tid = threadIdx.x;
#pragma unroll
    for (int i = 0; i < 16; i++) Bs[tid + i * 256] = B[tid + i * 256];
    __syncthreads();
    int r = tid >> 2, c0 = (tid & 3) * 16;
    float acc[16];
#pragma unroll
    for (int j = 0; j < 16; j++) acc[j] = 0.f;
    for (int k = 0; k < FD; k++) {
        float a = A[r * FD + k];
#pragma unroll
        for (int j = 0; j < 16; j++) acc[j] = fmaf(a, Bs[k * FD + c0 + j], acc[j]);
    }
#pragma unroll
    for (int j = 0; j < 16; j++) C[r * FD + c0 + j] = acc[j];
}

// split one W into bf16 hi/lo planes [k][72], wide uint4 stores.
// thread t handles 8 consecutive nn of row k: t = k*8 + (nn/8)
__device__ __forceinline__ void wsplit_one(const float* __restrict__ src, int slot,
                                           int tid) {
#pragma unroll
    for (int i = 0; i < 2; i++) {
        int t = tid + i * 256;          // 0..511
        int k = t >> 3, g = t & 7;
        uint32_t hi[4], lo[4];
#pragma unroll
        for (int p = 0; p < 4; p++) {
            float v0 = src[k * FD + g * 8 + 2 * p];
            float v1 = src[k * FD + g * 8 + 2 * p + 1];
            float h0 = bfhi(v0), h1 = bfhi(v1);
            hi[p] = packbf(h0, h1);
            lo[p] = packbf(v0 - h0, v1 - h1);
        }
        // byte offset k*144 + g*16 -> uint4 index (k*9 + g)  [144 = 72*2]
        ((uint4*)&g_wpH[slot][0])[k * 9 + g] = make_uint4(hi[0], hi[1], hi[2], hi[3]);
        ((uint4*)&g_wpL[slot][0])[k * 9 + g] = make_uint4(lo[0], lo[1], lo[2], lo[3]);
    }
}

// blocks 0-2: split W1/W2/pW2 ; blocks 3-5: BN folds + fused bias
__global__ void k_prep(const float* W1, const float* W2, const float* pW2,
                       const float* b1, const float* g1, const float* bb1,
                       const float* m1, const float* v1,
                       const float* b2, const float* g2, const float* bb2,
                       const float* m2, const float* v2,
                       const float* b3, const float* pW1, const float* pb1) {
    int bx = blockIdx.x;
    if (bx < 3) {
        const float* src = (bx == 0) ? W1 : (bx == 1) ? W2 : pW2;
        int slot = (bx == 2) ? 3 : bx;
        wsplit_one(src, slot, threadIdx.x);
        return;
    }
    int c = threadIdx.x;
    if (c >= FD) return;
    if (bx == 3) {
        float s = g1[c] * rsqrtf(v1[c] + BN_EPS);
        g_scale1[c] = s;
        g_shift1[c] = (b1[c] - m1[c]) * s + bb1[c];
    } else if (bx == 4) {
        float s = g2[c] * rsqrtf(v2[c] + BN_EPS);
        g_scale2[c] = s;
        g_shift2[c] = (b2[c] - m2[c]) * s + bb2[c];
    } else {
        float s = pb1[c];
        for (int k = 0; k < FD; k++) s += b3[k] * pW1[k * FD + c];
        g_fb[c] = s;
    }
}

__global__ void k_wsplit_wm() { wsplit_one(g_Wm, 2, threadIdx.x); }

// ---------------- scans ----------------
__global__ void k_scan1(int n) {
    __shared__ int s[256];
    int i = blockIdx.x * 256 + threadIdx.x;
    int v = (i < n) ? g_cnt[i] : 0;
    if (i < n) g_dis[i] = rsqrtf((float)(v + 1));   // +1 self loop
    s[threadIdx.x] = v;
    __syncthreads();
#pragma unroll
    for (int off = 1; off < 256; off <<= 1) {
        int t = (threadIdx.x >= off) ? s[threadIdx.x - off] : 0;
        __syncthreads();
        s[threadIdx.x] += t;
        __syncthreads();
    }
    if (i < n) g_off[i + 1] = s[threadIdx.x];
    if (threadIdx.x == 255) g_bsum[blockIdx.x] = s[255];
}

__global__ void k_scan2(int nb) {
    __shared__ int s[512];
    int t = threadIdx.x;
    int v = (t < nb) ? g_bsum[t] : 0;
    s[t] = v;
    __syncthreads();
#pragma unroll
    for (int off = 1; off < 512; off <<= 1) {
        int u = (t >= off) ? s[t - off] : 0;
        __syncthreads();
        s[t] += u;
        __syncthreads();
    }
    if (t < nb) g_bsum[t] = s[t] - v;   // exclusive
}

__global__ void k_scan3(int n) {
    int i = blockIdx.x * blockDim.x + threadIdx.x;
    if (i < n) {
        int off = g_off[i + 1] + g_bsum[i >> 8];
        g_off[i + 1] = off;
        g_cursor[i] = off - g_cnt[i];
    }
    if (i == 0) g_off[0] = 0;
}

__global__ void k_fill(const void* ei, int E) {
    int e = blockIdx.x * blockDim.x + threadIdx.x;
    if (e >= E) return;
    int s = load_idx(ei, e);
    int d = load_idx(ei, (long long)E + e);
    float norm = g_dis[s] * g_dis[d];
    int pos = atomicAdd(&g_cursor[d], 1);
    g_csr[pos] = (ULL)(unsigned int)s | ((ULL)__float_as_uint(norm) << 32);
}

// ================= tensor-core GEMM (HMMA, split-bf16, prestaged W) =============
// Y[n,64] = X[n,64] @ W[64,64] (+bias). One 128-row tile per block, 256 threads.
// X = Xhi + Xlo bf16 built in smem; W hi/lo planes uint4-copied from global.
// D = XhWh + XhWl + XlWh fp32 via mma.m16n8k16. Layout identical to round 8.

#define LDA 72
#define OFF_ALO (128 * LDA * 2)           // 18432
#define OFF_WHI (2 * 128 * LDA * 2)       // 36864
#define WPLANE  (64 * LDA * 2)            // 9216
#define OFF_WLO (OFF_WHI + WPLANE)
#define TC_SMEM (OFF_WHI + 2 * WPLANE)    // 55296

__device__ __forceinline__ uint32_t smem_u32(const void* p) {
    uint32_t a;
    asm("{ .reg .u64 t; cvta.to.shared.u64 t, %1; cvt.u32.u64 %0, t; }"
        : "=r"(a) : "l"(p));
    return a;
}
__device__ __forceinline__ void ldmA(uint32_t addr, uint32_t r[4]) {
    asm volatile("ldmatrix.sync.aligned.m8n8.x4.shared.b16 {%0,%1,%2,%3}, [%4];"
                 : "=r"(r[0]), "=r"(r[1]), "=r"(r[2]), "=r"(r[3]) : "r"(addr));
}
__device__ __forceinline__ void ldmBT(uint32_t addr, uint32_t r[4]) {
    asm volatile("ldmatrix.sync.aligned.m8n8.x4.trans.shared.b16 {%0,%1,%2,%3}, [%4];"
                 : "=r"(r[0]), "=r"(r[1]), "=r"(r[2]), "=r"(r[3]) : "r"(addr));
}
__device__ __forceinline__ void hmma(float d[4], const uint32_t a[4],
                                     uint32_t b0, uint32_t b1) {
    asm volatile(
        "mma.sync.aligned.m16n8k16.row.col.f32.bf16.bf16.f32 "
        "{%0,%1,%2,%3}, {%4,%5,%6,%7}, {%8,%9}, {%0,%1,%2,%3};"
        : "+f"(d[0]), "+f"(d[1]), "+f"(d[2]), "+f"(d[3])
        : "r"(a[0]), "r"(a[1]), "r"(a[2]), "r"(a[3]), "r"(b0), "r"(b1));
}

// EPI: 0 = none, 1 = +bias
template <int EPI>
__global__ void __launch_bounds__(256)
k_gemm_mma(const float* __restrict__ X,
           const uint4* __restrict__ whp, const uint4* __restrict__ wlp,
           const float* __restrict__ bias, float* __restrict__ Y, int n) {
    extern __shared__ char smem[];
    uint32_t sb = smem_u32(smem);
    int tid = threadIdx.x, w = tid >> 5, lane = tid & 31;
    int row0 = blockIdx.x * 128;

    // ---- W planes: coalesced uint4 copy (576 each) ----
#pragma unroll
    for (int i = 0; i < 3; i++) {
        int idx = tid + i * 256;
        if (idx < 576) {
            ((uint4*)(smem + OFF_WHI))[idx] = whp[idx];
            ((uint4*)(smem + OFF_WLO))[idx] = wlp[idx];
        }
    }
    // ---- X tile split -> smem [r][k], 1024 groups of 8 floats, 4/thread ----
#pragma unroll
    for (int i = 0; i < 4; i++) {
        int t = tid + i * 256;
        int r = t >> 3, g = t & 7;
        int row = row0 + r;
        float4 a = make_float4(0.f, 0.f, 0.f, 0.f), b = a;
        if (row < n) {
            const float4* xp = (const float4*)(X + (size_t)row * FD + g * 8);
            a = xp[0]; b = xp[1];
        }
        float f[8] = {a.x, a.y, a.z, a.w, b.x, b.y, b.z, b.w};
        uint32_t hi[4], lo[4];
#pragma unroll
        for (int p = 0; p < 4; p++) {
            float h0 = bfhi(f[2 * p]), h1 = bfhi(f[2 * p + 1]);
            hi[p] = packbf(h0, h1);
            lo[p] = packbf(f[2 * p] - h0, f[2 * p + 1] - h1);
        }
        int off = r * (LDA * 2) + g * 16;
        *(uint4*)(smem + off) = make_uint4(hi[0], hi[1], hi[2], hi[3]);
        *(uint4*)(smem + OFF_ALO + off) = make_uint4(lo[0], lo[1], lo[2], lo[3]);
    }
    __syncthreads();

    uint32_t aA = sb + ((w * 16 + (lane & 15)) * LDA + (lane >> 4) * 8) * 2;
    uint32_t aAl = aA + OFF_ALO;
    uint32_t aB = sb + OFF_WHI + ((lane & 15) * LDA + (lane >> 4) * 8) * 2;
    uint32_t aBl = aB + WPLANE;

    float acc[8][4];
#pragma unroll
    for (int i = 0; i < 8; i++)
#pragma unroll
        for (int j = 0; j < 4; j++) acc[i][j] = 0.f;

#pragma unroll
    for (int ks = 0; ks < 4; ks++) {
        uint32_t ah[4], al[4];
        ldmA(aA + ks * 32, ah);            // +16 bf16 cols per k-step
        ldmA(aAl + ks * 32, al);
        uint32_t krow = ks * 16 * LDA * 2;
#pragma unroll
        for (int pr = 0; pr < 4; pr++) {   // ntile pair: cols pr*16 .. pr*16+15
            uint32_t bh[4], bl[4];
            ldmBT(aB + krow + pr * 32, bh);
            ldmBT(aBl + krow + pr * 32, bl);
            int nt = pr * 2;
            hmma(acc[nt],     ah, bh[0], bh[1]);
            hmma(acc[nt],     ah, bl[0], bl[1]);
            hmma(acc[nt],     al, bh[0], bh[1]);
            hmma(acc[nt + 1], ah, bh[2], bh[3]);
            hmma(acc[nt + 1], ah, bl[2], bl[3]);
            hmma(acc[nt + 1], al, bh[2], bh[3]);
        }
    }

    // epilogue: C layout m16n8.f32 — {c0,c1} at (lane/4, 2*(lane%4)), {c2,c3} at row+8
    int r0 = row0 + w * 16 + (lane >> 2);
    int cbase = (lane & 3) * 2;
#pragma unroll
    for (int half = 0; half < 2; half++) {
        int row = r0 + half * 8;
        if (row >= n) continue;
        float* yr = Y + (size_t)row * FD;
#pragma unroll
        for (int nt = 0; nt < 8; nt++) {
            int c = nt * 8 + cbase;
            float2 v = make_float2(acc[nt][2 * half], acc[nt][2 * half + 1]);
            if (EPI == 1) { v.x += bias[c]; v.y += bias[c + 1]; }
            *(float2*)(yr + c) = v;
        }
    }
}

// ---------------- gather aggregation (CSR), fused self-loop + epilogue ----------
// One warp per node; lane handles cols [2*lane, 2*lane+1].
// EPI: 0 = plain, 1 = BN1+ReLU, 2 = BN2+ReLU, 3 = tanh(. + fb)
template <int EPI>
__global__ void __launch_bounds__(256)
k_gather(const float* __restrict__ h, float* __restrict__ out, int n) {
    int node = (blockIdx.x * blockDim.x + threadIdx.x) >> 5;
    int lane = threadIdx.x & 31;
    if (node >= n) return;

    const float2* hp = (const float2*)h;
    float d = g_dis[node];
    float2 acc = hp[(size_t)node * 32 + lane];
    float s2 = d * d;
    acc.x *= s2; acc.y *= s2;

    int e = g_off[node], end = g_off[node + 1];

    for (; e + 4 <= end; e += 4) {
        ULL e0 = g_csr[e + 0];
        ULL e1 = g_csr[e + 1];
        ULL e2 = g_csr[e + 2];
        ULL e3 = g_csr[e + 3];
        float2 v0 = hp[(size_t)(unsigned)e0 * 32 + lane];
        float2 v1 = hp[(size_t)(unsigned)e1 * 32 + lane];
        float2 v2 = hp[(size_t)(unsigned)e2 * 32 + lane];
        float2 v3 = hp[(size_t)(unsigned)e3 * 32 + lane];
        float n0 = __uint_as_float((unsigned)(e0 >> 32));
        float n1 = __uint_as_float((unsigned)(e1 >> 32));
        float n2 = __uint_as_float((unsigned)(e2 >> 32));
        float n3 = __uint_as_float((unsigned)(e3 >> 32));
        acc.x = fmaf(v0.x, n0, acc.x); acc.y = fmaf(v0.y, n0, acc.y);
        acc.x = fmaf(v1.x, n1, acc.x); acc.y = fmaf(v1.y, n1, acc.y);
        acc.x = fmaf(v2.x, n2, acc.x); acc.y = fmaf(v2.y, n2, acc.y);
        acc.x = fmaf(v3.x, n3, acc.x); acc.y = fmaf(v3.y, n3, acc.y);
    }
    for (; e < end; e++) {
        ULL e0 = g_csr[e];
        float2 v0 = hp[(size_t)(unsigned)e0 * 32 + lane];
        float n0 = __uint_as_float((unsigned)(e0 >> 32));
        acc.x = fmaf(v0.x, n0, acc.x); acc.y = fmaf(v0.y, n0, acc.y);
    }

    int c = lane * 2;
    if (EPI == 1) {
        acc.x = fmaxf(fmaf(acc.x, g_scale1[c],     g_shift1[c]),     0.f);
        acc.y = fmaxf(fmaf(acc.y, g_scale1[c + 1], g_shift1[c + 1]), 0.f);
    } else if (EPI == 2) {
        acc.x = fmaxf(fmaf(acc.x, g_scale2[c],     g_shift2[c]),     0.f);
        acc.y = fmaxf(fmaf(acc.y, g_scale2[c + 1], g_shift2[c + 1]), 0.f);
    } else if (EPI == 3) {
        acc.x = tanhf(acc.x + g_fb[c]);
        acc.y = tanhf(acc.y + g_fb[c + 1]);
    }
    ((float2*)out)[(size_t)node * 32 + lane] = acc;
}

// ---------------- launch ----------------
extern "C" void kernel_launch(void* const* d_in, const int* in_sizes, int n_in,
                              void* d_out, int out_size) {
    const float* x    = (const float*)d_in[0];
    const void*  ei   = d_in[1];
    const float* W1   = (const float*)d_in[2];
    const float* b1   = (const float*)d_in[3];
    const float* W2   = (const float*)d_in[4];
    const float* b2   = (const float*)d_in[5];
    const float* W3   = (const float*)d_in[6];
    const float* b3   = (const float*)d_in[7];
    const float* bn1g = (const float*)d_in[8];
    const float* bn1b = (const float*)d_in[9];
    const float* bn1m = (const float*)d_in[10];
    const float* bn1v = (const float*)d_in[11];
    const float* bn2g = (const float*)d_in[12];
    const float* bn2b = (const float*)d_in[13];
    const float* bn2m = (const float*)d_in[14];
    const float* bn2v = (const float*)d_in[15];
    const float* pW1  = (const float*)d_in[16];
    const float* pb1  = (const float*)d_in[17];
    const float* pW2  = (const float*)d_in[18];
    const float* pb2  = (const float*)d_in[19];
    float* out = (float*)d_out;

    int n = in_sizes[0] / FD;
    int E = in_sizes[1] / 2;
    if (n > MAXN) n = MAXN;
    if (E > MAXE) E = MAXE;

    float *H, *G, *WM;
    uint4 *WPH, *WPL;
    cudaGetSymbolAddress((void**)&H,   g_H);
    cudaGetSymbolAddress((void**)&G,   g_G);
    cudaGetSymbolAddress((void**)&WM,  g_Wm);
    cudaGetSymbolAddress((void**)&WPH, g_wpH);
    cudaGetSymbolAddress((void**)&WPL, g_wpL);

    cudaFuncSetAttribute(k_gemm_mma<0>, cudaFuncAttributeMaxDynamicSharedMemorySize, TC_SMEM);
    cudaFuncSetAttribute(k_gemm_mma<1>, cudaFuncAttributeMaxDynamicSharedMemorySize, TC_SMEM);

    const int TB = 256;
    int gb_n   = (n + TB - 1) / TB;
    int gb_e   = (E + TB - 1) / TB;
    int ntiles = (n + 127) / 128;         // 128-row gemm tiles
    int gb_w   = (n + 7) / 8;             // gather blocks (8 warps/block)
    int nb     = (n + 255) / 256;         // scan blocks

    // 1..3: init / count / prep (W planes for W1,W2,pW2 + BN folds + fb)
    k_init<<<gb_n, TB>>>((const unsigned int*)ei, n);
    k_count<<<gb_e, TB>>>(ei, E);
    k_prep<<<6, TB>>>(W1, W2, pW2,
                      b1, bn1g, bn1b, bn1m, bn1v,
                      b2, bn2g, bn2b, bn2m, bn2v,
                      b3, pW1, pb1);

    // 4: GEMM1 (profiled launch) — independent of CSR
    k_gemm_mma<0><<<ntiles, TB, TC_SMEM>>>(x, WPH + 0, WPL + 0, nullptr, H, n);

    // 5..6: Wm = W3 @ pW1, split into slot 2
    k_mm64<<<1, TB>>>(W3, pW1, WM);
    k_wsplit_wm<<<1, TB>>>();

    // 7..10: CSR build
    k_scan1<<<nb, 256>>>(n);
    k_scan2<<<1, 512>>>(nb);
    k_scan3<<<gb_n, TB>>>(n);
    k_fill<<<gb_e, TB>>>(ei, E);

    // layer 1 aggregation + BN1/ReLU
    k_gather<1><<<gb_w, TB>>>(H, G, n);

    // layer 2
    k_gemm_mma<0><<<ntiles, TB, TC_SMEM>>>(G, WPH + 576, WPL + 576, nullptr, H, n);
    k_gather<2><<<gb_w, TB>>>(H, G, n);

    // layer 3 + predictor-GEMM1 merged: T = tanh(agg(G @ Wm) + fb)
    k_gemm_mma<0><<<ntiles, TB, TC_SMEM>>>(G, WPH + 1152, WPL + 1152, nullptr, H, n);
    k_gather<3><<<gb_w, TB>>>(H, G, n);

    // predictor output GEMM
    k_gemm_mma<1><<<ntiles, TB, TC_SMEM>>>(G, WPH + 1728, WPL + 1728, pb2, out, n);
}

// round 12
// speedup vs baseline: 1.3771x; 1.0456x over previous
#include <cuda_runtime.h>
#include <cuda_bf16.h>
#include <math.h>
#include <stdint.h>

#define MAXN 100000
#define MAXE 800000
#define FD 64
#define BN_EPS 1e-5f

typedef unsigned long long ULL;

// ---------------- scratch (no allocations allowed) ----------------
__device__ int   g_cnt[MAXN];
__device__ int   g_off[MAXN + 1];
__device__ int   g_cursor[MAXN];
__device__ int   g_bsum[512];
__device__ float g_dis[MAXN];
__device__ ULL   g_csr[MAXE];     // packed {src:int, norm:float}
__device__ float g_H[(size_t)MAXN * FD];
__device__ float g_G[(size_t)MAXN * FD];
// W bf16 hi/lo planes, layout [k][72] bf16 (=576 uint4); slots 0=W1,1=W2,2=Wm,3=pW2
__device__ uint4 g_wpH[4][576];
__device__ uint4 g_wpL[4][576];
__device__ float g_scale1[FD], g_shift1[FD];
__device__ float g_scale2[FD], g_shift2[FD];
__device__ float g_fb[FD];
__device__ int   g_is64;

// ---------------- init: zero counts + edge dtype detect ----------------
__global__ void k_init(const unsigned int* ei, int n) {
    int i = blockIdx.x * blockDim.x + threadIdx.x;
    if (i < n) g_cnt[i] = 0;
    if (i == 0) {
        int is64 = 1;
        for (int j = 1; j < 64; j += 2)
            if (ei[j] != 0u) { is64 = 0; break; }
        g_is64 = is64;
    }
}

__device__ __forceinline__ int load_idx(const void* ei, long long pos) {
    if (g_is64) return (int)((const long long*)ei)[pos];
    return ((const int*)ei)[pos];
}

__global__ void k_count(const void* ei, int E) {
    int e = blockIdx.x * blockDim.x + threadIdx.x;
    if (e >= E) return;
    int dst = load_idx(ei, (long long)E + e);
    atomicAdd(&g_cnt[dst], 1);
}

// ---------------- helpers ----------------
__device__ __forceinline__ uint32_t packbf(float a, float b) {
    uint32_t r;
    asm("cvt.rn.bf16x2.f32 %0, %1, %2;" : "=r"(r) : "f"(b), "f"(a));  // lo=a, hi=b
    return r;
}
__device__ __forceinline__ float bfhi(float v) {
    return __bfloat162float(__float2bfloat16(v));
}

// split one W into bf16 hi/lo planes [k][72], wide uint4 stores.
__device__ __forceinline__ void wsplit_one(const float* __restrict__ src, int slot,
                                           int tid) {
#pragma unroll
    for (int i = 0; i < 2; i++) {
        int t = tid + i * 256;          // 0..511
        int k = t >> 3, g = t & 7;
        uint32_t hi[4], lo[4];
#pragma unroll
        for (int p = 0; p < 4; p++) {
            float v0 = src[k * FD + g * 8 + 2 * p];
            float v1 = src[k * FD + g * 8 + 2 * p + 1];
            float h0 = bfhi(v0), h1 = bfhi(v1);
            hi[p] = packbf(h0, h1);
            lo[p] = packbf(v0 - h0, v1 - h1);
        }
        ((uint4*)&g_wpH[slot][0])[k * 9 + g] = make_uint4(hi[0], hi[1], hi[2], hi[3]);
        ((uint4*)&g_wpL[slot][0])[k * 9 + g] = make_uint4(lo[0], lo[1], lo[2], lo[3]);
    }
}

// blocks 0-2: split W1/W2/pW2 ; 3-4: BN folds ; 5: fused bias ; 6: Wm=W3@pW1 + split
__global__ void k_prep(const float* W1, const float* W2, const float* pW2,
                       const float* W3, const float* pW1,
                       const float* b1, const float* g1, const float* bb1,
                       const float* m1, const float* v1,
                       const float* b2, const float* g2, const float* bb2,
                       const float* m2, const float* v2,
                       const float* b3, const float* pb1) {
    int bx = blockIdx.x;
    int tid = threadIdx.x;
    if (bx < 3) {
        const float* src = (bx == 0) ? W1 : (bx == 1) ? W2 : pW2;
        int slot = (bx == 2) ? 3 : bx;
        wsplit_one(src, slot, tid);
        return;
    }
    if (bx == 6) {
        // Wm = W3 @ pW1 into smem, then split to slot 2
        __shared__ float Bs[FD * FD];
        __shared__ float Wm_s[FD * FD];
#pragma unroll
        for (int i = 0; i < 16; i++) Bs[tid + i * 256] = pW1[tid + i * 256];
        __syncthreads();
        int r = tid >> 2, c0 = (tid & 3) * 16;
        float acc[16];
#pragma unroll
        for (int j = 0; j < 16; j++) acc[j] = 0.f;
        for (int k = 0; k < FD; k++) {
            float a = W3[r * FD + k];
#pragma unroll
            for (int j = 0; j < 16; j++) acc[j] = fmaf(a, Bs[k * FD + c0 + j], acc[j]);
        }
#pragma unroll
        for (int j = 0; j < 16; j++) Wm_s[r * FD + c0 + j] = acc[j];
        __syncthreads();
        wsplit_one(Wm_s, 2, tid);
        return;
    }
    int c = tid;
    if (c >= FD) return;
    if (bx == 3) {
        float s = g1[c] * rsqrtf(v1[c] + BN_EPS);
        g_scale1[c] = s;
        g_shift1[c] = (b1[c] - m1[c]) * s + bb1[c];
    } else if (bx == 4) {
        float s = g2[c] * rsqrtf(v2[c] + BN_EPS);
        g_scale2[c] = s;
        g_shift2[c] = (b2[c] - m2[c]) * s + bb2[c];
    } else {
        float s = pb1[c];
        for (int k = 0; k < FD; k++) s += b3[k] * pW1[k * FD + c];
        g_fb[c] = s;
    }
}

// ---------------- scans ----------------
__global__ void k_scan1(int n) {
    __shared__ int s[256];
    int i = blockIdx.x * 256 + threadIdx.x;
    int v = (i < n) ? g_cnt[i] : 0;
    if (i < n) g_dis[i] = rsqrtf((float)(v + 1));   // +1 self loop
    s[threadIdx.x] = v;
    __syncthreads();
#pragma unroll
    for (int off = 1; off < 256; off <<= 1) {
        int t = (threadIdx.x >= off) ? s[threadIdx.x - off] : 0;
        __syncthreads();
        s[threadIdx.x] += t;
        __syncthreads();
    }
    if (i < n) g_off[i + 1] = s[threadIdx.x];
    if (threadIdx.x == 255) g_bsum[blockIdx.x] = s[255];
}

__global__ void k_scan2(int nb) {
    __shared__ int s[512];
    int t = threadIdx.x;
    int v = (t < nb) ? g_bsum[t] : 0;
    s[t] = v;
    __syncthreads();
#pragma unroll
    for (int off = 1; off < 512; off <<= 1) {
        int u = (t >= off) ? s[t - off] : 0;
        __syncthreads();
        s[t] += u;
        __syncthreads();
    }
    if (t < nb) g_bsum[t] = s[t] - v;   // exclusive
}

__global__ void k_scan3(int n) {
    int i = blockIdx.x * blockDim.x + threadIdx.x;
    if (i < n) {
        int off = g_off[i + 1] + g_bsum[i >> 8];
        g_off[i + 1] = off;
        g_cursor[i] = off - g_cnt[i];
    }
    if (i == 0) g_off[0] = 0;
}

__global__ void k_fill(const void* ei, int E) {
    int e = blockIdx.x * blockDim.x + threadIdx.x;
    if (e >= E) return;
    int s = load_idx(ei, e);
    int d = load_idx(ei, (long long)E + e);
    float norm = g_dis[s] * g_dis[d];
    int pos = atomicAdd(&g_cursor[d], 1);
    g_csr[pos] = (ULL)(unsigned int)s | ((ULL)__float_as_uint(norm) << 32);
}

// ================= tensor-core GEMM (HMMA, split-bf16, prestaged W) =============
// Y[n,64] = X[n,64] @ W[64,64] (+bias). 128-row tiles, grid-stride over tiles
// (one balanced wave, W planes loaded once per block). 256 threads / block.
// X = Xhi + Xlo bf16 built in smem; D = XhWh + XhWl + XlWh fp32 via mma.m16n8k16.

#define LDA 72
#define OFF_ALO (128 * LDA * 2)           // 18432
#define OFF_WHI (2 * 128 * LDA * 2)       // 36864
#define WPLANE  (64 * LDA * 2)            // 9216
#define OFF_WLO (OFF_WHI + WPLANE)
#define TC_SMEM (OFF_WHI + 2 * WPLANE)    // 55296

__device__ __forceinline__ uint32_t smem_u32(const void* p) {
    uint32_t a;
    asm("{ .reg .u64 t; cvta.to.shared.u64 t, %1; cvt.u32.u64 %0, t; }"
        : "=r"(a) : "l"(p));
    return a;
}
__device__ __forceinline__ void ldmA(uint32_t addr, uint32_t r[4]) {
    asm volatile("ldmatrix.sync.aligned.m8n8.x4.shared.b16 {%0,%1,%2,%3}, [%4];"
                 : "=r"(r[0]), "=r"(r[1]), "=r"(r[2]), "=r"(r[3]) : "r"(addr));
}
__device__ __forceinline__ void ldmBT(uint32_t addr, uint32_t r[4]) {
    asm volatile("ldmatrix.sync.aligned.m8n8.x4.trans.shared.b16 {%0,%1,%2,%3}, [%4];"
                 : "=r"(r[0]), "=r"(r[1]), "=r"(r[2]), "=r"(r[3]) : "r"(addr));
}
__device__ __forceinline__ void hmma(float d[4], const uint32_t a[4],
                                     uint32_t b0, uint32_t b1) {
    asm volatile(
        "mma.sync.aligned.m16n8k16.row.col.f32.bf16.bf16.f32 "
        "{%0,%1,%2,%3}, {%4,%5,%6,%7}, {%8,%9}, {%0,%1,%2,%3};"
        : "+f"(d[0]), "+f"(d[1]), "+f"(d[2]), "+f"(d[3])
        : "r"(a[0]), "r"(a[1]), "r"(a[2]), "r"(a[3]), "r"(b0), "r"(b1));
}

// EPI: 0 = none, 1 = +bias
template <int EPI>
__global__ void __launch_bounds__(256)
k_gemm_mma(const float* __restrict__ X,
           const uint4* __restrict__ whp, const uint4* __restrict__ wlp,
           const float* __restrict__ bias, float* __restrict__ Y,
           int n, int ntiles) {
    extern __shared__ char smem[];
    uint32_t sb = smem_u32(smem);
    int tid = threadIdx.x, w = tid >> 5, lane = tid & 31;

    // ---- W planes: coalesced uint4 copy (576 each), once per block ----
#pragma unroll
    for (int i = 0; i < 3; i++) {
        int idx = tid + i * 256;
        if (idx < 576) {
            ((uint4*)(smem + OFF_WHI))[idx] = whp[idx];
            ((uint4*)(smem + OFF_WLO))[idx] = wlp[idx];
        }
    }

    uint32_t aA0 = sb + ((w * 16 + (lane & 15)) * LDA + (lane >> 4) * 8) * 2;
    uint32_t aB = sb + OFF_WHI + ((lane & 15) * LDA + (lane >> 4) * 8) * 2;
    uint32_t aBl = aB + WPLANE;
    int cbase = (lane & 3) * 2;

    for (int t = blockIdx.x; t < ntiles; t += gridDim.x) {
        int row0 = t * 128;
        __syncthreads();     // W visibility (first iter) + A-smem reuse safety

        // ---- X tile split -> smem [r][k] ----
#pragma unroll
        for (int i = 0; i < 4; i++) {
            int tt = tid + i * 256;
            int r = tt >> 3, g = tt & 7;
            int row = row0 + r;
            float4 a = make_float4(0.f, 0.f, 0.f, 0.f), b = a;
            if (row < n) {
                const float4* xp = (const float4*)(X + (size_t)row * FD + g * 8);
                a = xp[0]; b = xp[1];
            }
            float f[8] = {a.x, a.y, a.z, a.w, b.x, b.y, b.z, b.w};
            uint32_t hi[4], lo[4];
#pragma unroll
            for (int p = 0; p < 4; p++) {
                float h0 = bfhi(f[2 * p]), h1 = bfhi(f[2 * p + 1]);
                hi[p] = packbf(h0, h1);
                lo[p] = packbf(f[2 * p] - h0, f[2 * p + 1] - h1);
            }
            int off = r * (LDA * 2) + g * 16;
            *(uint4*)(smem + off) = make_uint4(hi[0], hi[1], hi[2], hi[3]);
            *(uint4*)(smem + OFF_ALO + off) = make_uint4(lo[0], lo[1], lo[2], lo[3]);
        }
        __syncthreads();

        float acc[8][4];
#pragma unroll
        for (int i = 0; i < 8; i++)
#pragma unroll
            for (int j = 0; j < 4; j++) acc[i][j] = 0.f;

#pragma unroll
        for (int ks = 0; ks < 4; ks++) {
            uint32_t ah[4], al[4];
            ldmA(aA0 + ks * 32, ah);
            ldmA(aA0 + OFF_ALO + ks * 32, al);
            uint32_t krow = ks * 16 * LDA * 2;
#pragma unroll
            for (int pr = 0; pr < 4; pr++) {
                uint32_t bh[4], bl[4];
                ldmBT(aB + krow + pr * 32, bh);
                ldmBT(aBl + krow + pr * 32, bl);
                int nt = pr * 2;
                hmma(acc[nt],     ah, bh[0], bh[1]);
                hmma(acc[nt],     ah, bl[0], bl[1]);
                hmma(acc[nt],     al, bh[0], bh[1]);
                hmma(acc[nt + 1], ah, bh[2], bh[3]);
                hmma(acc[nt + 1], ah, bl[2], bl[3]);
                hmma(acc[nt + 1], al, bh[2], bh[3]);
            }
        }

        // epilogue: {c0,c1} at (lane/4, 2*(lane%4)), {c2,c3} at row+8
        int r0 = row0 + w * 16 + (lane >> 2);
#pragma unroll
        for (int half = 0; half < 2; half++) {
            int row = r0 + half * 8;
            if (row >= n) continue;
            float* yr = Y + (size_t)row * FD;
#pragma unroll
            for (int nt = 0; nt < 8; nt++) {
                int c = nt * 8 + cbase;
                float2 v = make_float2(acc[nt][2 * half], acc[nt][2 * half + 1]);
                if (EPI == 1) { v.x += bias[c]; v.y += bias[c + 1]; }
                *(float2*)(yr + c) = v;
            }
        }
    }
}

// ---------------- gather aggregation (CSR), fused self-loop + epilogue ----------
// One warp per node; lane handles cols [2*lane, 2*lane+1].
// EPI: 0 = plain, 1 = BN1+ReLU, 2 = BN2+ReLU, 3 = tanh(. + fb)
template <int EPI>
__global__ void __launch_bounds__(256)
k_gather(const float* __restrict__ h, float* __restrict__ out, int n) {
    int node = (blockIdx.x * blockDim.x + threadIdx.x) >> 5;
    int lane = threadIdx.x & 31;
    if (node >= n) return;

    const float2* hp = (const float2*)h;
    float d = g_dis[node];
    float2 acc = hp[(size_t)node * 32 + lane];
    float s2 = d * d;
    acc.x *= s2; acc.y *= s2;

    int e = g_off[node], end = g_off[node + 1];

    for (; e + 4 <= end; e += 4) {
        ULL e0 = g_csr[e + 0];
        ULL e1 = g_csr[e + 1];
        ULL e2 = g_csr[e + 2];
        ULL e3 = g_csr[e + 3];
        float2 v0 = hp[(size_t)(unsigned)e0 * 32 + lane];
        float2 v1 = hp[(size_t)(unsigned)e1 * 32 + lane];
        float2 v2 = hp[(size_t)(unsigned)e2 * 32 + lane];
        float2 v3 = hp[(size_t)(unsigned)e3 * 32 + lane];
        float n0 = __uint_as_float((unsigned)(e0 >> 32));
        float n1 = __uint_as_float((unsigned)(e1 >> 32));
        float n2 = __uint_as_float((unsigned)(e2 >> 32));
        float n3 = __uint_as_float((unsigned)(e3 >> 32));
        acc.x = fmaf(v0.x, n0, acc.x); acc.y = fmaf(v0.y, n0, acc.y);
        acc.x = fmaf(v1.x, n1, acc.x); acc.y = fmaf(v1.y, n1, acc.y);
        acc.x = fmaf(v2.x, n2, acc.x); acc.y = fmaf(v2.y, n2, acc.y);
        acc.x = fmaf(v3.x, n3, acc.x); acc.y = fmaf(v3.y, n3, acc.y);
    }
    for (; e < end; e++) {
        ULL e0 = g_csr[e];
        float2 v0 = hp[(size_t)(unsigned)e0 * 32 + lane];
        float n0 = __uint_as_float((unsigned)(e0 >> 32));
        acc.x = fmaf(v0.x, n0, acc.x); acc.y = fmaf(v0.y, n0, acc.y);
    }

    int c = lane * 2;
    if (EPI == 1) {
        acc.x = fmaxf(fmaf(acc.x, g_scale1[c],     g_shift1[c]),     0.f);
        acc.y = fmaxf(fmaf(acc.y, g_scale1[c + 1], g_shift1[c + 1]), 0.f);
    } else if (EPI == 2) {
        acc.x = fmaxf(fmaf(acc.x, g_scale2[c],     g_shift2[c]),     0.f);
        acc.y = fmaxf(fmaf(acc.y, g_scale2[c + 1], g_shift2[c + 1]), 0.f);
    } else if (EPI == 3) {
        acc.x = tanhf(acc.x + g_fb[c]);
        acc.y = tanhf(acc.y + g_fb[c + 1]);
    }
    ((float2*)out)[(size_t)node * 32 + lane] = acc;
}

// ---------------- launch ----------------
extern "C" void kernel_launch(void* const* d_in, const int* in_sizes, int n_in,
                              void* d_out, int out_size) {
    const float* x    = (const float*)d_in[0];
    const void*  ei   = d_in[1];
    const float* W1   = (const float*)d_in[2];
    const float* b1   = (const float*)d_in[3];
    const float* W2   = (const float*)d_in[4];
    const float* b2   = (const float*)d_in[5];
    const float* W3   = (const float*)d_in[6];
    const float* b3   = (const float*)d_in[7];
    const float* bn1g = (const float*)d_in[8];
    const float* bn1b = (const float*)d_in[9];
    const float* bn1m = (const float*)d_in[10];
    const float* bn1v = (const float*)d_in[11];
    const float* bn2g = (const float*)d_in[12];
    const float* bn2b = (const float*)d_in[13];
    const float* bn2m = (const float*)d_in[14];
    const float* bn2v = (const float*)d_in[15];
    const float* pW1  = (const float*)d_in[16];
    const float* pb1  = (const float*)d_in[17];
    const float* pW2  = (const float*)d_in[18];
    const float* pb2  = (const float*)d_in[19];
    float* out = (float*)d_out;

    int n = in_sizes[0] / FD;
    int E = in_sizes[1] / 2;
    if (n > MAXN) n = MAXN;
    if (E > MAXE) E = MAXE;

    float *H, *G;
    uint4 *WPH, *WPL;
    cudaGetSymbolAddress((void**)&H,   g_H);
    cudaGetSymbolAddress((void**)&G,   g_G);
    cudaGetSymbolAddress((void**)&WPH, g_wpH);
    cudaGetSymbolAddress((void**)&WPL, g_wpL);

    cudaFuncSetAttribute(k_gemm_mma<0>, cudaFuncAttributeMaxDynamicSharedMemorySize, TC_SMEM);
    cudaFuncSetAttribute(k_gemm_mma<1>, cudaFuncAttributeMaxDynamicSharedMemorySize, TC_SMEM);

    const int TB = 256;
    int gb_n   = (n + TB - 1) / TB;
    int gb_e   = (E + TB - 1) / TB;
    int ntiles = (n + 127) / 128;              // 128-row gemm tiles
    int gb_g   = (ntiles < 592) ? ntiles : 592; // one balanced wave (4 blk/SM x 148)
    int gb_w   = (n + 7) / 8;                  // gather blocks (8 warps/block)
    int nb     = (n + 255) / 256;              // scan blocks

    // 1..3: init / count / prep (W planes incl. Wm, BN folds, fb)
    k_init<<<gb_n, TB>>>((const unsigned int*)ei, n);
    k_count<<<gb_e, TB>>>(ei, E);
    k_prep<<<7, TB>>>(W1, W2, pW2, W3, pW1,
                      b1, bn1g, bn1b, bn1m, bn1v,
                      b2, bn2g, bn2b, bn2m, bn2v,
                      b3, pb1);

    // 4: GEMM1 (profiled launch) — independent of CSR
    k_gemm_mma<0><<<gb_g, TB, TC_SMEM>>>(x, WPH + 0, WPL + 0, nullptr, H, n, ntiles);

    // 5..8: CSR build
    k_scan1<<<nb, 256>>>(n);
    k_scan2<<<1, 512>>>(nb);
    k_scan3<<<gb_n, TB>>>(n);
    k_fill<<<gb_e, TB>>>(ei, E);

    // layer 1 aggregation + BN1/ReLU
    k_gather<1><<<gb_w, TB>>>(H, G, n);

    // layer 2
    k_gemm_mma<0><<<gb_g, TB, TC_SMEM>>>(G, WPH + 576, WPL + 576, nullptr, H, n, ntiles);
    k_gather<2><<<gb_w, TB>>>(H, G, n);

    // layer 3 + predictor-GEMM1 merged: T = tanh(agg(G @ Wm) + fb)
    k_gemm_mma<0><<<gb_g, TB, TC_SMEM>>>(G, WPH + 1152, WPL + 1152, nullptr, H, n, ntiles);
    k_gather<3><<<gb_w, TB>>>(H, G, n);

    // predictor output GEMM
    k_gemm_mma<1><<<gb_g, TB, TC_SMEM>>>(G, WPH + 1728, WPL + 1728, pb2, out, n, ntiles);
}

// round 13
// speedup vs baseline: 1.3778x; 1.0005x over previous
#include <cuda_runtime.h>
#include <cuda_bf16.h>
#include <cuda_fp16.h>
#include <math.h>
#include <stdint.h>

#define MAXN 100000
#define MAXE 800000
#define FD 64
#define BN_EPS 1e-5f

typedef unsigned long long ULL;

// ---------------- scratch (no allocations allowed) ----------------
__device__ int    g_cnt[MAXN];
__device__ int    g_off[MAXN + 1];
__device__ int    g_cursor[MAXN];
__device__ int    g_bsum[512];
__device__ float  g_dis[MAXN];
__device__ ULL    g_csr[MAXE];     // packed {src:int, norm:float}
__device__ __half g_Hh[(size_t)MAXN * FD];   // fp16 GEMM->gather intermediate
__device__ float  g_G[(size_t)MAXN * FD];    // fp32 gather->GEMM intermediate
// W bf16 hi/lo planes, layout [k][72] bf16 (=576 uint4); slots 0=W1,1=W2,2=Wm,3=pW2
__device__ uint4  g_wpH[4][576];
__device__ uint4  g_wpL[4][576];
__device__ float  g_scale1[FD], g_shift1[FD];
__device__ float  g_scale2[FD], g_shift2[FD];
__device__ float  g_fb[FD];
__device__ int    g_is64;

// ---------------- init: zero counts + edge dtype detect ----------------
__global__ void k_init(const unsigned int* ei, int n) {
    int i = blockIdx.x * blockDim.x + threadIdx.x;
    if (i < n) g_cnt[i] = 0;
    if (i == 0) {
        int is64 = 1;
        for (int j = 1; j < 64; j += 2)
            if (ei[j] != 0u) { is64 = 0; break; }
        g_is64 = is64;
    }
}

__device__ __forceinline__ int load_idx(const void* ei, long long pos) {
    if (g_is64) return (int)((const long long*)ei)[pos];
    return ((const int*)ei)[pos];
}

__global__ void k_count(const void* ei, int E) {
    int e = blockIdx.x * blockDim.x + threadIdx.x;
    if (e >= E) return;
    int dst = load_idx(ei, (long long)E + e);
    atomicAdd(&g_cnt[dst], 1);
}

// ---------------- helpers ----------------
__device__ __forceinline__ uint32_t packbf(float a, float b) {
    uint32_t r;
    asm("cvt.rn.bf16x2.f32 %0, %1, %2;" : "=r"(r) : "f"(b), "f"(a));  // lo=a, hi=b
    return r;
}
__device__ __forceinline__ float bfhi(float v) {
    return __bfloat162float(__float2bfloat16(v));
}

// split one W into bf16 hi/lo planes [k][72], wide uint4 stores.
__device__ __forceinline__ void wsplit_one(const float* __restrict__ src, int slot,
                                           int tid) {
#pragma unroll
    for (int i = 0; i < 2; i++) {
        int t = tid + i * 256;          // 0..511
        int k = t >> 3, g = t & 7;
        uint32_t hi[4], lo[4];
#pragma unroll
        for (int p = 0; p < 4; p++) {
            float v0 = src[k * FD + g * 8 + 2 * p];
            float v1 = src[k * FD + g * 8 + 2 * p + 1];
            float h0 = bfhi(v0), h1 = bfhi(v1);
            hi[p] = packbf(h0, h1);
            lo[p] = packbf(v0 - h0, v1 - h1);
        }
        ((uint4*)&g_wpH[slot][0])[k * 9 + g] = make_uint4(hi[0], hi[1], hi[2], hi[3]);
        ((uint4*)&g_wpL[slot][0])[k * 9 + g] = make_uint4(lo[0], lo[1], lo[2], lo[3]);
    }
}

// blocks 0-2: split W1/W2/pW2 ; 3-4: BN folds ; 5: fused bias ; 6: Wm=W3@pW1 + split
__global__ void k_prep(const float* W1, const float* W2, const float* pW2,
                       const float* W3, const float* pW1,
                       const float* b1, const float* g1, const float* bb1,
                       const float* m1, const float* v1,
                       const float* b2, const float* g2, const float* bb2,
                       const float* m2, const float* v2,
                       const float* b3, const float* pb1) {
    int bx = blockIdx.x;
    int tid = threadIdx.x;
    if (bx < 3) {
        const float* src = (bx == 0) ? W1 : (bx == 1) ? W2 : pW2;
        int slot = (bx == 2) ? 3 : bx;
        wsplit_one(src, slot, tid);
        return;
    }
    if (bx == 6) {
        __shared__ float Bs[FD * FD];
        __shared__ float Wm_s[FD * FD];
#pragma unroll
        for (int i = 0; i < 16; i++) Bs[tid + i * 256] = pW1[tid + i * 256];
        __syncthreads();
        int r = tid >> 2, c0 = (tid & 3) * 16;
        float acc[16];
#pragma unroll
        for (int j = 0; j < 16; j++) acc[j] = 0.f;
        for (int k = 0; k < FD; k++) {
            float a = W3[r * FD + k];
#pragma unroll
            for (int j = 0; j < 16; j++) acc[j] = fmaf(a, Bs[k * FD + c0 + j], acc[j]);
        }
#pragma unroll
        for (int j = 0; j < 16; j++) Wm_s[r * FD + c0 + j] = acc[j];
        __syncthreads();
        wsplit_one(Wm_s, 2, tid);
        return;
    }
    int c = tid;
    if (c >= FD) return;
    if (bx == 3) {
        float s = g1[c] * rsqrtf(v1[c] + BN_EPS);
        g_scale1[c] = s;
        g_shift1[c] = (b1[c] - m1[c]) * s + bb1[c];
    } else if (bx == 4) {
        float s = g2[c] * rsqrtf(v2[c] + BN_EPS);
        g_scale2[c] = s;
        g_shift2[c] = (b2[c] - m2[c]) * s + bb2[c];
    } else {
        float s = pb1[c];
        for (int k = 0; k < FD; k++) s += b3[k] * pW1[k * FD + c];
        g_fb[c] = s;
    }
}

// ---------------- scans ----------------
__global__ void k_scan1(int n) {
    __shared__ int s[256];
    int i = blockIdx.x * 256 + threadIdx.x;
    int v = (i < n) ? g_cnt[i] : 0;
    if (i < n) g_dis[i] = rsqrtf((float)(v + 1));   // +1 self loop
    s[threadIdx.x] = v;
    __syncthreads();
#pragma unroll
    for (int off = 1; off < 256; off <<= 1) {
        int t = (threadIdx.x >= off) ? s[threadIdx.x - off] : 0;
        __syncthreads();
        s[threadIdx.x] += t;
        __syncthreads();
    }
    if (i < n) g_off[i + 1] = s[threadIdx.x];
    if (threadIdx.x == 255) g_bsum[blockIdx.x] = s[255];
}

__global__ void k_scan2(int nb) {
    __shared__ int s[512];
    int t = threadIdx.x;
    int v = (t < nb) ? g_bsum[t] : 0;
    s[t] = v;
    __syncthreads();
#pragma unroll
    for (int off = 1; off < 512; off <<= 1) {
        int u = (t >= off) ? s[t - off] : 0;
        __syncthreads();
        s[t] += u;
        __syncthreads();
    }
    if (t < nb) g_bsum[t] = s[t] - v;   // exclusive
}

__global__ void k_scan3(int n) {
    int i = blockIdx.x * blockDim.x + threadIdx.x;
    if (i < n) {
        int off = g_off[i + 1] + g_bsum[i >> 8];
        g_off[i + 1] = off;
        g_cursor[i] = off - g_cnt[i];
    }
    if (i == 0) g_off[0] = 0;
}

__global__ void k_fill(const void* ei, int E) {
    int e = blockIdx.x * blockDim.x + threadIdx.x;
    if (e >= E) return;
    int s = load_idx(ei, e);
    int d = load_idx(ei, (long long)E + e);
    float norm = g_dis[s] * g_dis[d];
    int pos = atomicAdd(&g_cursor[d], 1);
    g_csr[pos] = (ULL)(unsigned int)s | ((ULL)__float_as_uint(norm) << 32);
}

// ================= tensor-core GEMM (HMMA, split-bf16, prestaged W) =============
// Y[n,64] = X[n,64] @ W[64,64] (+epilogue). One 128-row tile per block, 256 thr.
// X fp32 -> split bf16 hi/lo in smem; W hi/lo planes uint4-copied from global.
// D = XhWh + XhWl + XlWh fp32 via mma.m16n8k16.
// OUTH=1: write fp16 (__half2 pairs). EPI: 0 = none, 1 = +bias.

#define LDA 72
#define OFF_ALO (128 * LDA * 2)           // 18432
#define OFF_WHI (2 * 128 * LDA * 2)       // 36864
#define WPLANE  (64 * LDA * 2)            // 9216
#define OFF_WLO (OFF_WHI + WPLANE)
#define TC_SMEM (OFF_WHI + 2 * WPLANE)    // 55296

__device__ __forceinline__ uint32_t smem_u32(const void* p) {
    uint32_t a;
    asm("{ .reg .u64 t; cvta.to.shared.u64 t, %1; cvt.u32.u64 %0, t; }"
        : "=r"(a) : "l"(p));
    return a;
}
__device__ __forceinline__ void ldmA(uint32_t addr, uint32_t r[4]) {
    asm volatile("ldmatrix.sync.aligned.m8n8.x4.shared.b16 {%0,%1,%2,%3}, [%4];"
                 : "=r"(r[0]), "=r"(r[1]), "=r"(r[2]), "=r"(r[3]) : "r"(addr));
}
__device__ __forceinline__ void ldmBT(uint32_t addr, uint32_t r[4]) {
    asm volatile("ldmatrix.sync.aligned.m8n8.x4.trans.shared.b16 {%0,%1,%2,%3}, [%4];"
                 : "=r"(r[0]), "=r"(r[1]), "=r"(r[2]), "=r"(r[3]) : "r"(addr));
}
__device__ __forceinline__ void hmma(float d[4], const uint32_t a[4],
                                     uint32_t b0, uint32_t b1) {
    asm volatile(
        "mma.sync.aligned.m16n8k16.row.col.f32.bf16.bf16.f32 "
        "{%0,%1,%2,%3}, {%4,%5,%6,%7}, {%8,%9}, {%0,%1,%2,%3};"
        : "+f"(d[0]), "+f"(d[1]), "+f"(d[2]), "+f"(d[3])
        : "r"(a[0]), "r"(a[1]), "r"(a[2]), "r"(a[3]), "r"(b0), "r"(b1));
}

template <int EPI, int OUTH>
__global__ void __launch_bounds__(256)
k_gemm_mma(const float* __restrict__ X,
           const uint4* __restrict__ whp, const uint4* __restrict__ wlp,
           const float* __restrict__ bias, void* __restrict__ Yv, int n) {
    extern __shared__ char smem[];
    uint32_t sb = smem_u32(smem);
    int tid = threadIdx.x, w = tid >> 5, lane = tid & 31;
    int row0 = blockIdx.x * 128;

    // ---- W planes: coalesced uint4 copy (576 each) ----
#pragma unroll
    for (int i = 0; i < 3; i++) {
        int idx = tid + i * 256;
        if (idx < 576) {
            ((uint4*)(smem + OFF_WHI))[idx] = whp[idx];
            ((uint4*)(smem + OFF_WLO))[idx] = wlp[idx];
        }
    }
    // ---- X tile split -> smem [r][k] ----
#pragma unroll
    for (int i = 0; i < 4; i++) {
        int t = tid + i * 256;
        int r = t >> 3, g = t & 7;
        int row = row0 + r;
        float4 a = make_float4(0.f, 0.f, 0.f, 0.f), b = a;
        if (row < n) {
            const float4* xp = (const float4*)(X + (size_t)row * FD + g * 8);
            a = xp[0]; b = xp[1];
        }
        float f[8] = {a.x, a.y, a.z, a.w, b.x, b.y, b.z, b.w};
        uint32_t hi[4], lo[4];
#pragma unroll
        for (int p = 0; p < 4; p++) {
            float h0 = bfhi(f[2 * p]), h1 = bfhi(f[2 * p + 1]);
            hi[p] = packbf(h0, h1);
            lo[p] = packbf(f[2 * p] - h0, f[2 * p + 1] - h1);
        }
        int off = r * (LDA * 2) + g * 16;
        *(uint4*)(smem + off) = make_uint4(hi[0], hi[1], hi[2], hi[3]);
        *(uint4*)(smem + OFF_ALO + off) = make_uint4(lo[0], lo[1], lo[2], lo[3]);
    }
    __syncthreads();

    uint32_t aA = sb + ((w * 16 + (lane & 15)) * LDA + (lane >> 4) * 8) * 2;
    uint32_t aAl = aA + OFF_ALO;
    uint32_t aB = sb + OFF_WHI + ((lane & 15) * LDA + (lane >> 4) * 8) * 2;
    uint32_t aBl = aB + WPLANE;

    float acc[8][4];
#pragma unroll
    for (int i = 0; i < 8; i++)
#pragma unroll
        for (int j = 0; j < 4; j++) acc[i][j] = 0.f;

#pragma unroll
    for (int ks = 0; ks < 4; ks++) {
        uint32_t ah[4], al[4];
        ldmA(aA + ks * 32, ah);
        ldmA(aAl + ks * 32, al);
        uint32_t krow = ks * 16 * LDA * 2;
#pragma unroll
        for (int pr = 0; pr < 4; pr++) {
            uint32_t bh[4], bl[4];
            ldmBT(aB + krow + pr * 32, bh);
            ldmBT(aBl + krow + pr * 32, bl);
            int nt = pr * 2;
            hmma(acc[nt],     ah, bh[0], bh[1]);
            hmma(acc[nt],     ah, bl[0], bl[1]);
            hmma(acc[nt],     al, bh[0], bh[1]);
            hmma(acc[nt + 1], ah, bh[2], bh[3]);
            hmma(acc[nt + 1], ah, bl[2], bl[3]);
            hmma(acc[nt + 1], al, bh[2], bh[3]);
        }
    }

    // epilogue: {c0,c1} at (lane/4, 2*(lane%4)), {c2,c3} at row+8
    int r0 = row0 + w * 16 + (lane >> 2);
    int cbase = (lane & 3) * 2;
#pragma unroll
    for (int half = 0; half < 2; half++) {
        int row = r0 + half * 8;
        if (row >= n) continue;
#pragma unroll
        for (int nt = 0; nt < 8; nt++) {
            int c = nt * 8 + cbase;
            float2 v = make_float2(acc[nt][2 * half], acc[nt][2 * half + 1]);
            if (EPI == 1) { v.x += bias[c]; v.y += bias[c + 1]; }
            if (OUTH) {
                __half* yr = ((__half*)Yv) + (size_t)row * FD;
                *(__half2*)(yr + c) = __floats2half2_rn(v.x, v.y);
            } else {
                float* yr = ((float*)Yv) + (size_t)row * FD;
                *(float2*)(yr + c) = v;
            }
        }
    }
}

// ---------------- gather aggregation (CSR), fp16 input, fp32 output -------------
// One warp per node; lane handles cols [2*lane, 2*lane+1].
// EPI: 1 = BN1+ReLU, 2 = BN2+ReLU, 3 = tanh(. + fb)
template <int EPI>
__global__ void __launch_bounds__(256)
k_gather(const __half* __restrict__ h, float* __restrict__ out, int n) {
    int node = (blockIdx.x * blockDim.x + threadIdx.x) >> 5;
    int lane = threadIdx.x & 31;
    if (node >= n) return;

    const __half2* hp = (const __half2*)h;
    float d = g_dis[node];
    float2 acc = __half22float2(hp[(size_t)node * 32 + lane]);
    float s2 = d * d;
    acc.x *= s2; acc.y *= s2;

    int e = g_off[node], end = g_off[node + 1];

    for (; e + 4 <= end; e += 4) {
        ULL e0 = g_csr[e + 0];
        ULL e1 = g_csr[e + 1];
        ULL e2 = g_csr[e + 2];
        ULL e3 = g_csr[e + 3];
        float2 v0 = __half22float2(hp[(size_t)(unsigned)e0 * 32 + lane]);
        float2 v1 = __half22float2(hp[(size_t)(unsigned)e1 * 32 + lane]);
        float2 v2 = __half22float2(hp[(size_t)(unsigned)e2 * 32 + lane]);
        float2 v3 = __half22float2(hp[(size_t)(unsigned)e3 * 32 + lane]);
        float n0 = __uint_as_float((unsigned)(e0 >> 32));
        float n1 = __uint_as_float((unsigned)(e1 >> 32));
        float n2 = __uint_as_float((unsigned)(e2 >> 32));
        float n3 = __uint_as_float((unsigned)(e3 >> 32));
        acc.x = fmaf(v0.x, n0, acc.x); acc.y = fmaf(v0.y, n0, acc.y);
        acc.x = fmaf(v1.x, n1, acc.x); acc.y = fmaf(v1.y, n1, acc.y);
        acc.x = fmaf(v2.x, n2, acc.x); acc.y = fmaf(v2.y, n2, acc.y);
        acc.x = fmaf(v3.x, n3, acc.x); acc.y = fmaf(v3.y, n3, acc.y);
    }
    for (; e < end; e++) {
        ULL e0 = g_csr[e];
        float2 v0 = __half22float2(hp[(size_t)(unsigned)e0 * 32 + lane]);
        float n0 = __uint_as_float((unsigned)(e0 >> 32));
        acc.x = fmaf(v0.x, n0, acc.x); acc.y = fmaf(v0.y, n0, acc.y);
    }

    int c = lane * 2;
    if (EPI == 1) {
        acc.x = fmaxf(fmaf(acc.x, g_scale1[c],     g_shift1[c]),     0.f);
        acc.y = fmaxf(fmaf(acc.y, g_scale1[c + 1], g_shift1[c + 1]), 0.f);
    } else if (EPI == 2) {
        acc.x = fmaxf(fmaf(acc.x, g_scale2[c],     g_shift2[c]),     0.f);
        acc.y = fmaxf(fmaf(acc.y, g_scale2[c + 1], g_shift2[c + 1]), 0.f);
    } else if (EPI == 3) {
        acc.x = tanhf(acc.x + g_fb[c]);
        acc.y = tanhf(acc.y + g_fb[c + 1]);
    }
    ((float2*)out)[(size_t)node * 32 + lane] = acc;
}

// ---------------- launch ----------------
extern "C" void kernel_launch(void* const* d_in, const int* in_sizes, int n_in,
                              void* d_out, int out_size) {
    const float* x    = (const float*)d_in[0];
    const void*  ei   = d_in[1];
    const float* W1   = (const float*)d_in[2];
    const float* b1   = (const float*)d_in[3];
    const float* W2   = (const float*)d_in[4];
    const float* b2   = (const float*)d_in[5];
    const float* W3   = (const float*)d_in[6];
    const float* b3   = (const float*)d_in[7];
    const float* bn1g = (const float*)d_in[8];
    const float* bn1b = (const float*)d_in[9];
    const float* bn1m = (const float*)d_in[10];
    const float* bn1v = (const float*)d_in[11];
    const float* bn2g = (const float*)d_in[12];
    const float* bn2b = (const float*)d_in[13];
    const float* bn2m = (const float*)d_in[14];
    const float* bn2v = (const float*)d_in[15];
    const float* pW1  = (const float*)d_in[16];
    const float* pb1  = (const float*)d_in[17];
    const float* pW2  = (const float*)d_in[18];
    const float* pb2  = (const float*)d_in[19];
    float* out = (float*)d_out;

    int n = in_sizes[0] / FD;
    int E = in_sizes[1] / 2;
    if (n > MAXN) n = MAXN;
    if (E > MAXE) E = MAXE;

    __half* Hh;
    float*  G;
    uint4 *WPH, *WPL;
    cudaGetSymbolAddress((void**)&Hh,  g_Hh);
    cudaGetSymbolAddress((void**)&G,   g_G);
    cudaGetSymbolAddress((void**)&WPH, g_wpH);
    cudaGetSymbolAddress((void**)&WPL, g_wpL);

    cudaFuncSetAttribute(k_gemm_mma<0,1>, cudaFuncAttributeMaxDynamicSharedMemorySize, TC_SMEM);
    cudaFuncSetAttribute(k_gemm_mma<1,0>, cudaFuncAttributeMaxDynamicSharedMemorySize, TC_SMEM);

    const int TB = 256;
    int gb_n   = (n + TB - 1) / TB;
    int gb_e   = (E + TB - 1) / TB;
    int ntiles = (n + 127) / 128;         // 128-row gemm tiles
    int gb_w   = (n + 7) / 8;             // gather blocks (8 warps/block)
    int nb     = (n + 255) / 256;         // scan blocks

    // 1..3: init / count / prep (W planes incl. Wm, BN folds, fb)
    k_init<<<gb_n, TB>>>((const unsigned int*)ei, n);
    k_count<<<gb_e, TB>>>(ei, E);
    k_prep<<<7, TB>>>(W1, W2, pW2, W3, pW1,
                      b1, bn1g, bn1b, bn1m, bn1v,
                      b2, bn2g, bn2b, bn2m, bn2v,
                      b3, pb1);

    // 4: GEMM1 (profiled launch) — independent of CSR; fp16 output
    k_gemm_mma<0,1><<<ntiles, TB, TC_SMEM>>>(x, WPH + 0, WPL + 0, nullptr, Hh, n);

    // 5..8: CSR build
    k_scan1<<<nb, 256>>>(n);
    k_scan2<<<1, 512>>>(nb);
    k_scan3<<<gb_n, TB>>>(n);
    k_fill<<<gb_e, TB>>>(ei, E);

    // layer 1 aggregation + BN1/ReLU (fp16 in, fp32 out)
    k_gather<1><<<gb_w, TB>>>(Hh, G, n);

    // layer 2
    k_gemm_mma<0,1><<<ntiles, TB, TC_SMEM>>>(G, WPH + 576, WPL + 576, nullptr, Hh, n);
    k_gather<2><<<gb_w, TB>>>(Hh, G, n);

    // layer 3 + predictor-GEMM1 merged: G = tanh(agg(G @ Wm) + fb)
    k_gemm_mma<0,1><<<ntiles, TB, TC_SMEM>>>(G, WPH + 1152, WPL + 1152, nullptr, Hh, n);
    k_gather<3><<<gb_w, TB>>>(Hh, G, n);

    // predictor output GEMM (fp32 out, +bias)
    k_gemm_mma<1,0><<<ntiles, TB, TC_SMEM>>>(G, WPH + 1728, WPL + 1728, pb2, out, n);
}

// round 14
// speedup vs baseline: 1.5140x; 1.0988x over previous
#include <cuda_runtime.h>
#include <cuda_bf16.h>
#include <cuda_fp16.h>
#include <math.h>
#include <stdint.h>

#define MAXN 100000
#define MAXE 800000
#define FD 64
#define BN_EPS 1e-5f

typedef unsigned long long ULL;

// ---------------- scratch (no allocations allowed) ----------------
__device__ int    g_cnt[MAXN];
__device__ int    g_off[MAXN + 1];
__device__ int    g_cursor[MAXN];
__device__ int    g_bsum[512];
__device__ float  g_dis[MAXN];
__device__ ULL    g_csr[MAXE];     // packed {src:int, norm:float}
__device__ __half g_Hh[(size_t)MAXN * FD];   // fp16 GEMM->gather intermediate
__device__ float  g_G[(size_t)MAXN * FD];    // fp32 gather->GEMM intermediate
// W bf16 hi/lo planes, layout [k][72] bf16 (=576 uint4); slots 0=W1,1=W2,2=Wm,3=pW2
__device__ uint4  g_wpH[4][576];
__device__ uint4  g_wpL[4][576];
__device__ float  g_scale1[FD], g_shift1[FD];
__device__ float  g_scale2[FD], g_shift2[FD];
__device__ float  g_fb[FD];
__device__ int    g_is64;

// ---------------- init: zero counts + edge dtype detect ----------------
__global__ void k_init(const unsigned int* ei, int n) {
    int i = blockIdx.x * blockDim.x + threadIdx.x;
    if (i < n) g_cnt[i] = 0;
    if (i == 0) {
        int is64 = 1;
        for (int j = 1; j < 64; j += 2)
            if (ei[j] != 0u) { is64 = 0; break; }
        g_is64 = is64;
    }
}

__device__ __forceinline__ int load_idx(const void* ei, long long pos) {
    if (g_is64) return (int)((const long long*)ei)[pos];
    return ((const int*)ei)[pos];
}

__global__ void k_count(const void* ei, int E) {
    int e = blockIdx.x * blockDim.x + threadIdx.x;
    if (e >= E) return;
    int dst = load_idx(ei, (long long)E + e);
    atomicAdd(&g_cnt[dst], 1);
}

// ---------------- helpers ----------------
__device__ __forceinline__ uint32_t packbf(float a, float b) {
    uint32_t r;
    asm("cvt.rn.bf16x2.f32 %0, %1, %2;" : "=r"(r) : "f"(b), "f"(a));  // lo=a, hi=b
    return r;
}
__device__ __forceinline__ float bfhi(float v) {
    return __bfloat162float(__float2bfloat16(v));
}

// split one W into bf16 hi/lo planes [k][72], wide uint4 stores.
__device__ __forceinline__ void wsplit_one(const float* __restrict__ src, int slot,
                                           int tid) {
#pragma unroll
    for (int i = 0; i < 2; i++) {
        int t = tid + i * 256;          // 0..511
        int k = t >> 3, g = t & 7;
        uint32_t hi[4], lo[4];
#pragma unroll
        for (int p = 0; p < 4; p++) {
            float v0 = src[k * FD + g * 8 + 2 * p];
            float v1 = src[k * FD + g * 8 + 2 * p + 1];
            float h0 = bfhi(v0), h1 = bfhi(v1);
            hi[p] = packbf(h0, h1);
            lo[p] = packbf(v0 - h0, v1 - h1);
        }
        ((uint4*)&g_wpH[slot][0])[k * 9 + g] = make_uint4(hi[0], hi[1], hi[2], hi[3]);
        ((uint4*)&g_wpL[slot][0])[k * 9 + g] = make_uint4(lo[0], lo[1], lo[2], lo[3]);
    }
}

// blocks 0-2: split W1/W2/pW2 ; 3-4: BN folds ; 5: fused bias ; 6: Wm=W3@pW1 + split
__global__ void k_prep(const float* W1, const float* W2, const float* pW2,
                       const float* W3, const float* pW1,
                       const float* b1, const float* g1, const float* bb1,
                       const float* m1, const float* v1,
                       const float* b2, const float* g2, const float* bb2,
                       const float* m2, const float* v2,
                       const float* b3, const float* pb1) {
    int bx = blockIdx.x;
    int tid = threadIdx.x;
    if (bx < 3) {
        const float* src = (bx == 0) ? W1 : (bx == 1) ? W2 : pW2;
        int slot = (bx == 2) ? 3 : bx;
        wsplit_one(src, slot, tid);
        return;
    }
    if (bx == 6) {
        __shared__ float Bs[FD * FD];
        __shared__ float Wm_s[FD * FD];
#pragma unroll
        for (int i = 0; i < 16; i++) Bs[tid + i * 256] = pW1[tid + i * 256];
        __syncthreads();
        int r = tid >> 2, c0 = (tid & 3) * 16;
        float acc[16];
#pragma unroll
        for (int j = 0; j < 16; j++) acc[j] = 0.f;
        for (int k = 0; k < FD; k++) {
            float a = W3[r * FD + k];
#pragma unroll
            for (int j = 0; j < 16; j++) acc[j] = fmaf(a, Bs[k * FD + c0 + j], acc[j]);
        }
#pragma unroll
        for (int j = 0; j < 16; j++) Wm_s[r * FD + c0 + j] = acc[j];
        __syncthreads();
        wsplit_one(Wm_s, 2, tid);
        return;
    }
    int c = tid;
    if (c >= FD) return;
    if (bx == 3) {
        float s = g1[c] * rsqrtf(v1[c] + BN_EPS);
        g_scale1[c] = s;
        g_shift1[c] = (b1[c] - m1[c]) * s + bb1[c];
    } else if (bx == 4) {
        float s = g2[c] * rsqrtf(v2[c] + BN_EPS);
        g_scale2[c] = s;
        g_shift2[c] = (b2[c] - m2[c]) * s + bb2[c];
    } else {
        float s = pb1[c];
        for (int k = 0; k < FD; k++) s += b3[k] * pW1[k * FD + c];
        g_fb[c] = s;
    }
}

// ---------------- scans ----------------
__global__ void k_scan1(int n) {
    __shared__ int s[256];
    int i = blockIdx.x * 256 + threadIdx.x;
    int v = (i < n) ? g_cnt[i] : 0;
    if (i < n) g_dis[i] = rsqrtf((float)(v + 1));   // +1 self loop
    s[threadIdx.x] = v;
    __syncthreads();
#pragma unroll
    for (int off = 1; off < 256; off <<= 1) {
        int t = (threadIdx.x >= off) ? s[threadIdx.x - off] : 0;
        __syncthreads();
        s[threadIdx.x] += t;
        __syncthreads();
    }
    if (i < n) g_off[i + 1] = s[threadIdx.x];
    if (threadIdx.x == 255) g_bsum[blockIdx.x] = s[255];
}

__global__ void k_scan2(int nb) {
    __shared__ int s[512];
    int t = threadIdx.x;
    int v = (t < nb) ? g_bsum[t] : 0;
    s[t] = v;
    __syncthreads();
#pragma unroll
    for (int off = 1; off < 512; off <<= 1) {
        int u = (t >= off) ? s[t - off] : 0;
        __syncthreads();
        s[t] += u;
        __syncthreads();
    }
    if (t < nb) g_bsum[t] = s[t] - v;   // exclusive
}

__global__ void k_scan3(int n) {
    int i = blockIdx.x * blockDim.x + threadIdx.x;
    if (i < n) {
        int off = g_off[i + 1] + g_bsum[i >> 8];
        g_off[i + 1] = off;
        g_cursor[i] = off - g_cnt[i];
    }
    if (i == 0) g_off[0] = 0;
}

__global__ void k_fill(const void* ei, int E) {
    int e = blockIdx.x * blockDim.x + threadIdx.x;
    if (e >= E) return;
    int s = load_idx(ei, e);
    int d = load_idx(ei, (long long)E + e);
    float norm = g_dis[s] * g_dis[d];
    int pos = atomicAdd(&g_cursor[d], 1);
    g_csr[pos] = (ULL)(unsigned int)s | ((ULL)__float_as_uint(norm) << 32);
}

// ================= tensor-core GEMM (HMMA, split-bf16, prestaged W) =============
// Y[n,64] = X[n,64] @ W[64,64] (+epilogue). One 128-row tile per block, 256 thr.
// X fp32 -> split bf16 hi/lo in smem; W hi/lo planes uint4-copied from global.
// D = XhWh + XhWl + XlWh fp32 via mma.m16n8k16.
// OUTH=1: write fp16 (__half2 pairs). EPI: 0 = none, 1 = +bias.

#define LDA 72
#define OFF_ALO (128 * LDA * 2)           // 18432
#define OFF_WHI (2 * 128 * LDA * 2)       // 36864
#define WPLANE  (64 * LDA * 2)            // 9216
#define OFF_WLO (OFF_WHI + WPLANE)
#define TC_SMEM (OFF_WHI + 2 * WPLANE)    // 55296

__device__ __forceinline__ uint32_t smem_u32(const void* p) {
    uint32_t a;
    asm("{ .reg .u64 t; cvta.to.shared.u64 t, %1; cvt.u32.u64 %0, t; }"
        : "=r"(a) : "l"(p));
    return a;
}
__device__ __forceinline__ void ldmA(uint32_t addr, uint32_t r[4]) {
    asm volatile("ldmatrix.sync.aligned.m8n8.x4.shared.b16 {%0,%1,%2,%3}, [%4];"
                 : "=r"(r[0]), "=r"(r[1]), "=r"(r[2]), "=r"(r[3]) : "r"(addr));
}
__device__ __forceinline__ void ldmBT(uint32_t addr, uint32_t r[4]) {
    asm volatile("ldmatrix.sync.aligned.m8n8.x4.trans.shared.b16 {%0,%1,%2,%3}, [%4];"
                 : "=r"(r[0]), "=r"(r[1]), "=r"(r[2]), "=r"(r[3]) : "r"(addr));
}
__device__ __forceinline__ void hmma(float d[4], const uint32_t a[4],
                                     uint32_t b0, uint32_t b1) {
    asm volatile(
        "mma.sync.aligned.m16n8k16.row.col.f32.bf16.bf16.f32 "
        "{%0,%1,%2,%3}, {%4,%5,%6,%7}, {%8,%9}, {%0,%1,%2,%3};"
        : "+f"(d[0]), "+f"(d[1]), "+f"(d[2]), "+f"(d[3])
        : "r"(a[0]), "r"(a[1]), "r"(a[2]), "r"(a[3]), "r"(b0), "r"(b1));
}

template <int EPI, int OUTH>
__global__ void __launch_bounds__(256)
k_gemm_mma(const float* __restrict__ X,
           const uint4* __restrict__ whp, const uint4* __restrict__ wlp,
           const float* __restrict__ bias, void* __restrict__ Yv, int n) {
    extern __shared__ char smem[];
    uint32_t sb = smem_u32(smem);
    int tid = threadIdx.x, w = tid >> 5, lane = tid & 31;
    int row0 = blockIdx.x * 128;

    // ---- W planes: coalesced uint4 copy (576 each) ----
#pragma unroll
    for (int i = 0; i < 3; i++) {
        int idx = tid + i * 256;
        if (idx < 576) {
            ((uint4*)(smem + OFF_WHI))[idx] = whp[idx];
            ((uint4*)(smem + OFF_WLO))[idx] = wlp[idx];
        }
    }
    // ---- X tile split -> smem [r][k] ----
#pragma unroll
    for (int i = 0; i < 4; i++) {
        int t = tid + i * 256;
        int r = t >> 3, g = t & 7;
        int row = row0 + r;
        float4 a = make_float4(0.f, 0.f, 0.f, 0.f), b = a;
        if (row < n) {
            const float4* xp = (const float4*)(X + (size_t)row * FD + g * 8);
            a = xp[0]; b = xp[1];
        }
        float f[8] = {a.x, a.y, a.z, a.w, b.x, b.y, b.z, b.w};
        uint32_t hi[4], lo[4];
#pragma unroll
        for (int p = 0; p < 4; p++) {
            float h0 = bfhi(f[2 * p]), h1 = bfhi(f[2 * p + 1]);
            hi[p] = packbf(h0, h1);
            lo[p] = packbf(f[2 * p] - h0, f[2 * p + 1] - h1);
        }
        int off = r * (LDA * 2) + g * 16;
        *(uint4*)(smem + off) = make_uint4(hi[0], hi[1], hi[2], hi[3]);
        *(uint4*)(smem + OFF_ALO + off) = make_uint4(lo[0], lo[1], lo[2], lo[3]);
    }
    __syncthreads();

    uint32_t aA = sb + ((w * 16 + (lane & 15)) * LDA + (lane >> 4) * 8) * 2;
    uint32_t aAl = aA + OFF_ALO;
    uint32_t aB = sb + OFF_WHI + ((lane & 15) * LDA + (lane >> 4) * 8) * 2;
    uint32_t aBl = aB + WPLANE;

    float acc[8][4];
#pragma unroll
    for (int i = 0; i < 8; i++)
#pragma unroll
        for (int j = 0; j < 4; j++) acc[i][j] = 0.f;

#pragma unroll
    for (int ks = 0; ks < 4; ks++) {
        uint32_t ah[4], al[4];
        ldmA(aA + ks * 32, ah);
        ldmA(aAl + ks * 32, al);
        uint32_t krow = ks * 16 * LDA * 2;
#pragma unroll
        for (int pr = 0; pr < 4; pr++) {
            uint32_t bh[4], bl[4];
            ldmBT(aB + krow + pr * 32, bh);
            ldmBT(aBl + krow + pr * 32, bl);
            int nt = pr * 2;
            hmma(acc[nt],     ah, bh[0], bh[1]);
            hmma(acc[nt],     ah, bl[0], bl[1]);
            hmma(acc[nt],     al, bh[0], bh[1]);
            hmma(acc[nt + 1], ah, bh[2], bh[3]);
            hmma(acc[nt + 1], ah, bl[2], bl[3]);
            hmma(acc[nt + 1], al, bh[2], bh[3]);
        }
    }

    // epilogue: {c0,c1} at (lane/4, 2*(lane%4)), {c2,c3} at row+8
    int r0 = row0 + w * 16 + (lane >> 2);
    int cbase = (lane & 3) * 2;
#pragma unroll
    for (int half = 0; half < 2; half++) {
        int row = r0 + half * 8;
        if (row >= n) continue;
#pragma unroll
        for (int nt = 0; nt < 8; nt++) {
            int c = nt * 8 + cbase;
            float2 v = make_float2(acc[nt][2 * half], acc[nt][2 * half + 1]);
            if (EPI == 1) { v.x += bias[c]; v.y += bias[c + 1]; }
            if (OUTH) {
                __half* yr = ((__half*)Yv) + (size_t)row * FD;
                *(__half2*)(yr + c) = __floats2half2_rn(v.x, v.y);
            } else {
                float* yr = ((float*)Yv) + (size_t)row * FD;
                *(float2*)(yr + c) = v;
            }
        }
    }
}

// ---------------- gather aggregation (CSR), fp16 in, fp32 out, 8 lanes/node -----
// 4 nodes per warp -> 4 independent load chains (4x MLP vs 1 node/warp).
// Lane group g = lane&7 covers cols [8g..8g+7] (one uint4 = 8 halves = full row
// across the group: 8 lanes x 16B = 128B = 1 cache line in fp16).
// EPI: 1 = BN1+ReLU, 2 = BN2+ReLU, 3 = tanh(. + fb)
__device__ __forceinline__ void cvt8(uint4 v, float f[8]) {
    float2 a = __half22float2(*(__half2*)&v.x);
    float2 b = __half22float2(*(__half2*)&v.y);
    float2 c = __half22float2(*(__half2*)&v.z);
    float2 d = __half22float2(*(__half2*)&v.w);
    f[0] = a.x; f[1] = a.y; f[2] = b.x; f[3] = b.y;
    f[4] = c.x; f[5] = c.y; f[6] = d.x; f[7] = d.y;
}

template <int EPI>
__global__ void __launch_bounds__(256)
k_gather(const __half* __restrict__ h, float* __restrict__ out, int n) {
    int t = blockIdx.x * blockDim.x + threadIdx.x;
    int node = t >> 3;              // 8 threads per node
    int g = threadIdx.x & 7;        // col chunk [8g..8g+7]
    if (node >= n) return;

    const uint4* hp = (const uint4*)h;   // row = 8 uint4
    float d = g_dis[node];
    float s2 = d * d;

    float acc[8];
    cvt8(hp[(size_t)node * 8 + g], acc);
#pragma unroll
    for (int j = 0; j < 8; j++) acc[j] *= s2;

    int e = g_off[node], end = g_off[node + 1];

    for (; e + 2 <= end; e += 2) {
        ULL e0 = g_csr[e];
        ULL e1 = g_csr[e + 1];
        uint4 r0 = hp[(size_t)(unsigned)e0 * 8 + g];
        uint4 r1 = hp[(size_t)(unsigned)e1 * 8 + g];
        float n0 = __uint_as_float((unsigned)(e0 >> 32));
        float n1 = __uint_as_float((unsigned)(e1 >> 32));
        float f0[8], f1[8];
        cvt8(r0, f0); cvt8(r1, f1);
#pragma unroll
        for (int j = 0; j < 8; j++) acc[j] = fmaf(f0[j], n0, acc[j]);
#pragma unroll
        for (int j = 0; j < 8; j++) acc[j] = fmaf(f1[j], n1, acc[j]);
    }
    if (e < end) {
        ULL e0 = g_csr[e];
        uint4 r0 = hp[(size_t)(unsigned)e0 * 8 + g];
        float n0 = __uint_as_float((unsigned)(e0 >> 32));
        float f0[8];
        cvt8(r0, f0);
#pragma unroll
        for (int j = 0; j < 8; j++) acc[j] = fmaf(f0[j], n0, acc[j]);
    }

    int c0 = g * 8;
    if (EPI == 1) {
#pragma unroll
        for (int j = 0; j < 8; j++)
            acc[j] = fmaxf(fmaf(acc[j], g_scale1[c0 + j], g_shift1[c0 + j]), 0.f);
    } else if (EPI == 2) {
#pragma unroll
        for (int j = 0; j < 8; j++)
            acc[j] = fmaxf(fmaf(acc[j], g_scale2[c0 + j], g_shift2[c0 + j]), 0.f);
    } else if (EPI == 3) {
#pragma unroll
        for (int j = 0; j < 8; j++)
            acc[j] = tanhf(acc[j] + g_fb[c0 + j]);
    }
    float4* op = (float4*)(out + (size_t)node * FD + c0);
    op[0] = make_float4(acc[0], acc[1], acc[2], acc[3]);
    op[1] = make_float4(acc[4], acc[5], acc[6], acc[7]);
}

// ---------------- launch ----------------
extern "C" void kernel_launch(void* const* d_in, const int* in_sizes, int n_in,
                              void* d_out, int out_size) {
    const float* x    = (const float*)d_in[0];
    const void*  ei   = d_in[1];
    const float* W1   = (const float*)d_in[2];
    const float* b1   = (const float*)d_in[3];
    const float* W2   = (const float*)d_in[4];
    const float* b2   = (const float*)d_in[5];
    const float* W3   = (const float*)d_in[6];
    const float* b3   = (const float*)d_in[7];
    const float* bn1g = (const float*)d_in[8];
    const float* bn1b = (const float*)d_in[9];
    const float* bn1m = (const float*)d_in[10];
    const float* bn1v = (const float*)d_in[11];
    const float* bn2g = (const float*)d_in[12];
    const float* bn2b = (const float*)d_in[13];
    const float* bn2m = (const float*)d_in[14];
    const float* bn2v = (const float*)d_in[15];
    const float* pW1  = (const float*)d_in[16];
    const float* pb1  = (const float*)d_in[17];
    const float* pW2  = (const float*)d_in[18];
    const float* pb2  = (const float*)d_in[19];
    float* out = (float*)d_out;

    int n = in_sizes[0] / FD;
    int E = in_sizes[1] / 2;
    if (n > MAXN) n = MAXN;
    if (E > MAXE) E = MAXE;

    __half* Hh;
    float*  G;
    uint4 *WPH, *WPL;
    cudaGetSymbolAddress((void**)&Hh,  g_Hh);
    cudaGetSymbolAddress((void**)&G,   g_G);
    cudaGetSymbolAddress((void**)&WPH, g_wpH);
    cudaGetSymbolAddress((void**)&WPL, g_wpL);

    cudaFuncSetAttribute(k_gemm_mma<0,1>, cudaFuncAttributeMaxDynamicSharedMemorySize, TC_SMEM);
    cudaFuncSetAttribute(k_gemm_mma<1,0>, cudaFuncAttributeMaxDynamicSharedMemorySize, TC_SMEM);

    const int TB = 256;
    int gb_n   = (n + TB - 1) / TB;
    int gb_e   = (E + TB - 1) / TB;
    int ntiles = (n + 127) / 128;               // 128-row gemm tiles
    int gb_w   = ((n * 8) + TB - 1) / TB;       // gather blocks (8 thr/node)
    int nb     = (n + 255) / 256;               // scan blocks

    // 1..3: init / count / prep (W planes incl. Wm, BN folds, fb)
    k_init<<<gb_n, TB>>>((const unsigned int*)ei, n);
    k_count<<<gb_e, TB>>>(ei, E);
    k_prep<<<7, TB>>>(W1, W2, pW2, W3, pW1,
                      b1, bn1g, bn1b, bn1m, bn1v,
                      b2, bn2g, bn2b, bn2m, bn2v,
                      b3, pb1);

    // 4: GEMM1 (profiled launch) — independent of CSR; fp16 output
    k_gemm_mma<0,1><<<ntiles, TB, TC_SMEM>>>(x, WPH + 0, WPL + 0, nullptr, Hh, n);

    // 5..8: CSR build
    k_scan1<<<nb, 256>>>(n);
    k_scan2<<<1, 512>>>(nb);
    k_scan3<<<gb_n, TB>>>(n);
    k_fill<<<gb_e, TB>>>(ei, E);

    // layer 1 aggregation + BN1/ReLU (fp16 in, fp32 out)
    k_gather<1><<<gb_w, TB>>>(Hh, G, n);

    // layer 2
    k_gemm_mma<0,1><<<ntiles, TB, TC_SMEM>>>(G, WPH + 576, WPL + 576, nullptr, Hh, n);
    k_gather<2><<<gb_w, TB>>>(Hh, G, n);

    // layer 3 + predictor-GEMM1 merged: G = tanh(agg(G @ Wm) + fb)
    k_gemm_mma<0,1><<<ntiles, TB, TC_SMEM>>>(G, WPH + 1152, WPL + 1152, nullptr, Hh, n);
    k_gather<3><<<gb_w, TB>>>(Hh, G, n);

    // predictor output GEMM (fp32 out, +bias)
    k_gemm_mma<1,0><<<ntiles, TB, TC_SMEM>>>(G, WPH + 1728, WPL + 1728, pb2, out, n);
}

// round 15
// speedup vs baseline: 1.6893x; 1.1158x over previous
#include <cuda_runtime.h>
#include <cuda_bf16.h>
#include <cuda_fp16.h>
#include <math.h>
#include <stdint.h>

#define MAXN 100000
#define MAXE 800000
#define FD 64
#define BN_EPS 1e-5f

typedef unsigned long long ULL;

// ---------------- scratch (no allocations allowed) ----------------
__device__ int    g_cnt[MAXN];
__device__ int    g_off[MAXN + 1];
__device__ int    g_cursor[MAXN];
__device__ int    g_bsum[512];
__device__ float  g_dis[MAXN];
__device__ ULL    g_csr[MAXE];     // packed {src:int, norm:float}
__device__ __half g_Hh[(size_t)MAXN * FD];   // fp16 GEMM->gather intermediate
__device__ __half g_Gh[(size_t)MAXN * FD];   // fp16 gather->GEMM intermediate
// W fp16 hi/lo planes, layout [k][72] fp16 (=576 uint4); slots 0=W1,1=W2,2=Wm,3=pW2
__device__ uint4  g_wpH[4][576];
__device__ uint4  g_wpL[4][576];
__device__ float  g_scale1[FD], g_shift1[FD];
__device__ float  g_scale2[FD], g_shift2[FD];
__device__ float  g_fb[FD];
__device__ int    g_is64;

// ---------------- init: zero counts + edge dtype detect ----------------
__global__ void k_init(const unsigned int* ei, int n) {
    int i = blockIdx.x * blockDim.x + threadIdx.x;
    if (i < n) g_cnt[i] = 0;
    if (i == 0) {
        int is64 = 1;
        for (int j = 1; j < 64; j += 2)
            if (ei[j] != 0u) { is64 = 0; break; }
        g_is64 = is64;
    }
}

__device__ __forceinline__ int load_idx(const void* ei, long long pos) {
    if (g_is64) return (int)((const long long*)ei)[pos];
    return ((const int*)ei)[pos];
}

__global__ void k_count(const void* ei, int E) {
    int e = blockIdx.x * blockDim.x + threadIdx.x;
    if (e >= E) return;
    int dst = load_idx(ei, (long long)E + e);
    atomicAdd(&g_cnt[dst], 1);
}

// ---------------- helpers ----------------
__device__ __forceinline__ uint32_t packh2(float a, float b) {
    __half2 h = __floats2half2_rn(a, b);
    return *(uint32_t*)&h;
}

// split one W into fp16 hi/lo planes [k][72], wide uint4 stores.
__device__ __forceinline__ void wsplit_one(const float* __restrict__ src, int slot,
                                           int tid) {
#pragma unroll
    for (int i = 0; i < 2; i++) {
        int t = tid + i * 256;          // 0..511
        int k = t >> 3, g = t & 7;
        uint32_t hi[4], lo[4];
#pragma unroll
        for (int p = 0; p < 4; p++) {
            float v0 = src[k * FD + g * 8 + 2 * p];
            float v1 = src[k * FD + g * 8 + 2 * p + 1];
            float h0 = __half2float(__float2half_rn(v0));
            float h1 = __half2float(__float2half_rn(v1));
            hi[p] = packh2(h0, h1);
            lo[p] = packh2(v0 - h0, v1 - h1);
        }
        ((uint4*)&g_wpH[slot][0])[k * 9 + g] = make_uint4(hi[0], hi[1], hi[2], hi[3]);
        ((uint4*)&g_wpL[slot][0])[k * 9 + g] = make_uint4(lo[0], lo[1], lo[2], lo[3]);
    }
}

// blocks 0-2: split W1/W2/pW2 ; 3-4: BN folds ; 5: fused bias ; 6: Wm=W3@pW1 + split
__global__ void k_prep(const float* W1, const float* W2, const float* pW2,
                       const float* W3, const float* pW1,
                       const float* b1, const float* g1, const float* bb1,
                       const float* m1, const float* v1,
                       const float* b2, const float* g2, const float* bb2,
                       const float* m2, const float* v2,
                       const float* b3, const float* pb1) {
    int bx = blockIdx.x;
    int tid = threadIdx.x;
    if (bx < 3) {
        const float* src = (bx == 0) ? W1 : (bx == 1) ? W2 : pW2;
        int slot = (bx == 2) ? 3 : bx;
        wsplit_one(src, slot, tid);
        return;
    }
    if (bx == 6) {
        __shared__ float Bs[FD * FD];
        __shared__ float Wm_s[FD * FD];
#pragma unroll
        for (int i = 0; i < 16; i++) Bs[tid + i * 256] = pW1[tid + i * 256];
        __syncthreads();
        int r = tid >> 2, c0 = (tid & 3) * 16;
        float acc[16];
#pragma unroll
        for (int j = 0; j < 16; j++) acc[j] = 0.f;
        for (int k = 0; k < FD; k++) {
            float a = W3[r * FD + k];
#pragma unroll
            for (int j = 0; j < 16; j++) acc[j] = fmaf(a, Bs[k * FD + c0 + j], acc[j]);
        }
#pragma unroll
        for (int j = 0; j < 16; j++) Wm_s[r * FD + c0 + j] = acc[j];
        __syncthreads();
        wsplit_one(Wm_s, 2, tid);
        return;
    }
    int c = tid;
    if (c >= FD) return;
    if (bx == 3) {
        float s = g1[c] * rsqrtf(v1[c] + BN_EPS);
        g_scale1[c] = s;
        g_shift1[c] = (b1[c] - m1[c]) * s + bb1[c];
    } else if (bx == 4) {
        float s = g2[c] * rsqrtf(v2[c] + BN_EPS);
        g_scale2[c] = s;
        g_shift2[c] = (b2[c] - m2[c]) * s + bb2[c];
    } else {
        float s = pb1[c];
        for (int k = 0; k < FD; k++) s += b3[k] * pW1[k * FD + c];
        g_fb[c] = s;
    }
}

// ---------------- scans ----------------
__global__ void k_scan1(int n) {
    __shared__ int s[256];
    int i = blockIdx.x * 256 + threadIdx.x;
    int v = (i < n) ? g_cnt[i] : 0;
    if (i < n) g_dis[i] = rsqrtf((float)(v + 1));   // +1 self loop
    s[threadIdx.x] = v;
    __syncthreads();
#pragma unroll
    for (int off = 1; off < 256; off <<= 1) {
        int t = (threadIdx.x >= off) ? s[threadIdx.x - off] : 0;
        __syncthreads();
        s[threadIdx.x] += t;
        __syncthreads();
    }
    if (i < n) g_off[i + 1] = s[threadIdx.x];
    if (threadIdx.x == 255) g_bsum[blockIdx.x] = s[255];
}

__global__ void k_scan2(int nb) {
    __shared__ int s[512];
    int t = threadIdx.x;
    int v = (t < nb) ? g_bsum[t] : 0;
    s[t] = v;
    __syncthreads();
#pragma unroll
    for (int off = 1; off < 512; off <<= 1) {
        int u = (t >= off) ? s[t - off] : 0;
        __syncthreads();
        s[t] += u;
        __syncthreads();
    }
    if (t < nb) g_bsum[t] = s[t] - v;   // exclusive
}

__global__ void k_scan3(int n) {
    int i = blockIdx.x * blockDim.x + threadIdx.x;
    if (i < n) {
        int off = g_off[i + 1] + g_bsum[i >> 8];
        g_off[i + 1] = off;
        g_cursor[i] = off - g_cnt[i];
    }
    if (i == 0) g_off[0] = 0;
}

__global__ void k_fill(const void* ei, int E) {
    int e = blockIdx.x * blockDim.x + threadIdx.x;
    if (e >= E) return;
    int s = load_idx(ei, e);
    int d = load_idx(ei, (long long)E + e);
    float norm = g_dis[s] * g_dis[d];
    int pos = atomicAdd(&g_cursor[d], 1);
    g_csr[pos] = (ULL)(unsigned int)s | ((ULL)__float_as_uint(norm) << 32);
}

// ================= tensor-core GEMM (HMMA fp16, W split hi/lo) =================
// Y[n,64] = X[n,64] @ W[64,64] (+epilogue). One 128-row tile per block, 256 thr.
// A = fp16 activations used verbatim (1 plane); W = Wh + Wl fp16 planes.
// D = A*Wh + A*Wl fp32 via mma.m16n8k16.f32.f16.f16.f32 (2 MMAs per step).
// INH: 1 = X fp16 (pure copy), 0 = X fp32 (convert). OUTH: 1 = fp16 out.
// EPI: 0 = none, 1 = +bias.

#define LDA 72
#define OFF_WHI (128 * LDA * 2)           // 18432
#define WPLANE  (64 * LDA * 2)            // 9216
#define OFF_WLO (OFF_WHI + WPLANE)
#define TC_SMEM (OFF_WHI + 2 * WPLANE)    // 36864

__device__ __forceinline__ uint32_t smem_u32(const void* p) {
    uint32_t a;
    asm("{ .reg .u64 t; cvta.to.shared.u64 t, %1; cvt.u32.u64 %0, t; }"
        : "=r"(a) : "l"(p));
    return a;
}
__device__ __forceinline__ void ldmA(uint32_t addr, uint32_t r[4]) {
    asm volatile("ldmatrix.sync.aligned.m8n8.x4.shared.b16 {%0,%1,%2,%3}, [%4];"
                 : "=r"(r[0]), "=r"(r[1]), "=r"(r[2]), "=r"(r[3]) : "r"(addr));
}
__device__ __forceinline__ void ldmBT(uint32_t addr, uint32_t r[4]) {
    asm volatile("ldmatrix.sync.aligned.m8n8.x4.trans.shared.b16 {%0,%1,%2,%3}, [%4];"
                 : "=r"(r[0]), "=r"(r[1]), "=r"(r[2]), "=r"(r[3]) : "r"(addr));
}
__device__ __forceinline__ void hmma16(float d[4], const uint32_t a[4],
                                       uint32_t b0, uint32_t b1) {
    asm volatile(
        "mma.sync.aligned.m16n8k16.row.col.f32.f16.f16.f32 "
        "{%0,%1,%2,%3}, {%4,%5,%6,%7}, {%8,%9}, {%0,%1,%2,%3};"
        : "+f"(d[0]), "+f"(d[1]), "+f"(d[2]), "+f"(d[3])
        : "r"(a[0]), "r"(a[1]), "r"(a[2]), "r"(a[3]), "r"(b0), "r"(b1));
}

template <int EPI, int INH, int OUTH>
__global__ void __launch_bounds__(256)
k_gemm_mma(const void* __restrict__ Xv,
           const uint4* __restrict__ whp, const uint4* __restrict__ wlp,
           const float* __restrict__ bias, void* __restrict__ Yv, int n) {
    extern __shared__ char smem[];
    uint32_t sb = smem_u32(smem);
    int tid = threadIdx.x, w = tid >> 5, lane = tid & 31;
    int row0 = blockIdx.x * 128;

    // ---- W planes: coalesced uint4 copy (576 each) ----
#pragma unroll
    for (int i = 0; i < 3; i++) {
        int idx = tid + i * 256;
        if (idx < 576) {
            ((uint4*)(smem + OFF_WHI))[idx] = whp[idx];
            ((uint4*)(smem + OFF_WLO))[idx] = wlp[idx];
        }
    }
    // ---- A tile -> smem [r][k] fp16 (1024 uint4-groups, 4/thread) ----
#pragma unroll
    for (int i = 0; i < 4; i++) {
        int t = tid + i * 256;
        int r = t >> 3, g = t & 7;
        int row = row0 + r;
        uint4 v = make_uint4(0u, 0u, 0u, 0u);
        if (row < n) {
            if (INH) {
                v = ((const uint4*)Xv)[(size_t)row * 8 + g];
            } else {
                const float4* xp = (const float4*)((const float*)Xv + (size_t)row * FD + g * 8);
                float4 a = xp[0], b = xp[1];
                v.x = packh2(a.x, a.y);
                v.y = packh2(a.z, a.w);
                v.z = packh2(b.x, b.y);
                v.w = packh2(b.z, b.w);
            }
        }
        *(uint4*)(smem + r * (LDA * 2) + g * 16) = v;
    }
    __syncthreads();

    uint32_t aA = sb + ((w * 16 + (lane & 15)) * LDA + (lane >> 4) * 8) * 2;
    uint32_t aB = sb + OFF_WHI + ((lane & 15) * LDA + (lane >> 4) * 8) * 2;
    uint32_t aBl = aB + WPLANE;

    float acc[8][4];
#pragma unroll
    for (int i = 0; i < 8; i++)
#pragma unroll
        for (int j = 0; j < 4; j++) acc[i][j] = 0.f;

#pragma unroll
    for (int ks = 0; ks < 4; ks++) {
        uint32_t ah[4];
        ldmA(aA + ks * 32, ah);            // +16 fp16 cols per k-step
        uint32_t krow = ks * 16 * LDA * 2;
#pragma unroll
        for (int pr = 0; pr < 4; pr++) {   // ntile pair: cols pr*16 .. pr*16+15
            uint32_t bh[4], bl[4];
            ldmBT(aB + krow + pr * 32, bh);
            ldmBT(aBl + krow + pr * 32, bl);
            int nt = pr * 2;
            hmma16(acc[nt],     ah, bh[0], bh[1]);
            hmma16(acc[nt],     ah, bl[0], bl[1]);
            hmma16(acc[nt + 1], ah, bh[2], bh[3]);
            hmma16(acc[nt + 1], ah, bl[2], bl[3]);
        }
    }

    // epilogue: {c0,c1} at (lane/4, 2*(lane%4)), {c2,c3} at row+8
    int r0 = row0 + w * 16 + (lane >> 2);
    int cbase = (lane & 3) * 2;
#pragma unroll
    for (int half = 0; half < 2; half++) {
        int row = r0 + half * 8;
        if (row >= n) continue;
#pragma unroll
        for (int nt = 0; nt < 8; nt++) {
            int c = nt * 8 + cbase;
            float2 v = make_float2(acc[nt][2 * half], acc[nt][2 * half + 1]);
            if (EPI == 1) { v.x += bias[c]; v.y += bias[c + 1]; }
            if (OUTH) {
                __half* yr = ((__half*)Yv) + (size_t)row * FD;
                *(__half2*)(yr + c) = __floats2half2_rn(v.x, v.y);
            } else {
                float* yr = ((float*)Yv) + (size_t)row * FD;
                *(float2*)(yr + c) = v;
            }
        }
    }
}

// ---------------- gather aggregation (CSR), fp16 in, fp16 out, 8 lanes/node -----
// 4 nodes per warp -> 4 independent load chains. Lane group g = lane&7 covers
// cols [8g..8g+7] (one uint4 = 8 halves; 8 lanes x 16B = 128B = full row).
// EPI: 1 = BN1+ReLU, 2 = BN2+ReLU, 3 = tanh(. + fb)
__device__ __forceinline__ void cvt8(uint4 v, float f[8]) {
    float2 a = __half22float2(*(__half2*)&v.x);
    float2 b = __half22float2(*(__half2*)&v.y);
    float2 c = __half22float2(*(__half2*)&v.z);
    float2 d = __half22float2(*(__half2*)&v.w);
    f[0] = a.x; f[1] = a.y; f[2] = b.x; f[3] = b.y;
    f[4] = c.x; f[5] = c.y; f[6] = d.x; f[7] = d.y;
}

template <int EPI>
__global__ void __launch_bounds__(256)
k_gather(const __half* __restrict__ h, __half* __restrict__ out, int n) {
    int t = blockIdx.x * blockDim.x + threadIdx.x;
    int node = t >> 3;              // 8 threads per node
    int g = threadIdx.x & 7;        // col chunk [8g..8g+7]
    if (node >= n) return;

    const uint4* hp = (const uint4*)h;   // row = 8 uint4
    float d = g_dis[node];
    float s2 = d * d;

    float acc[8];
    cvt8(hp[(size_t)node * 8 + g], acc);
#pragma unroll
    for (int j = 0; j < 8; j++) acc[j] *= s2;

    int e = g_off[node], end = g_off[node + 1];

    for (; e + 2 <= end; e += 2) {
        ULL e0 = g_csr[e];
        ULL e1 = g_csr[e + 1];
        uint4 r0 = hp[(size_t)(unsigned)e0 * 8 + g];
        uint4 r1 = hp[(size_t)(unsigned)e1 * 8 + g];
        float n0 = __uint_as_float((unsigned)(e0 >> 32));
        float n1 = __uint_as_float((unsigned)(e1 >> 32));
        float f0[8], f1[8];
        cvt8(r0, f0); cvt8(r1, f1);
#pragma unroll
        for (int j = 0; j < 8; j++) acc[j] = fmaf(f0[j], n0, acc[j]);
#pragma unroll
        for (int j = 0; j < 8; j++) acc[j] = fmaf(f1[j], n1, acc[j]);
    }
    if (e < end) {
        ULL e0 = g_csr[e];
        uint4 r0 = hp[(size_t)(unsigned)e0 * 8 + g];
        float n0 = __uint_as_float((unsigned)(e0 >> 32));
        float f0[8];
        cvt8(r0, f0);
#pragma unroll
        for (int j = 0; j < 8; j++) acc[j] = fmaf(f0[j], n0, acc[j]);
    }

    int c0 = g * 8;
    if (EPI == 1) {
#pragma unroll
        for (int j = 0; j < 8; j++)
            acc[j] = fmaxf(fmaf(acc[j], g_scale1[c0 + j], g_shift1[c0 + j]), 0.f);
    } else if (EPI == 2) {
#pragma unroll
        for (int j = 0; j < 8; j++)
            acc[j] = fmaxf(fmaf(acc[j], g_scale2[c0 + j], g_shift2[c0 + j]), 0.f);
    } else if (EPI == 3) {
#pragma unroll
        for (int j = 0; j < 8; j++)
            acc[j] = tanhf(acc[j] + g_fb[c0 + j]);
    }
    uint4 st;
    st.x = packh2(acc[0], acc[1]);
    st.y = packh2(acc[2], acc[3]);
    st.z = packh2(acc[4], acc[5]);
    st.w = packh2(acc[6], acc[7]);
    ((uint4*)out)[(size_t)node * 8 + g] = st;
}

// ---------------- launch ----------------
extern "C" void kernel_launch(void* const* d_in, const int* in_sizes, int n_in,
                              void* d_out, int out_size) {
    const float* x    = (const float*)d_in[0];
    const void*  ei   = d_in[1];
    const float* W1   = (const float*)d_in[2];
    const float* b1   = (const float*)d_in[3];
    const float* W2   = (const float*)d_in[4];
    const float* b2   = (const float*)d_in[5];
    const float* W3   = (const float*)d_in[6];
    const float* b3   = (const float*)d_in[7];
    const float* bn1g = (const float*)d_in[8];
    const float* bn1b = (const float*)d_in[9];
    const float* bn1m = (const float*)d_in[10];
    const float* bn1v = (const float*)d_in[11];
    const float* bn2g = (const float*)d_in[12];
    const float* bn2b = (const float*)d_in[13];
    const float* bn2m = (const float*)d_in[14];
    const float* bn2v = (const float*)d_in[15];
    const float* pW1  = (const float*)d_in[16];
    const float* pb1  = (const float*)d_in[17];
    const float* pW2  = (const float*)d_in[18];
    const float* pb2  = (const float*)d_in[19];
    float* out = (float*)d_out;

    int n = in_sizes[0] / FD;
    int E = in_sizes[1] / 2;
    if (n > MAXN) n = MAXN;
    if (E > MAXE) E = MAXE;

    __half *Hh, *Gh;
    uint4 *WPH, *WPL;
    cudaGetSymbolAddress((void**)&Hh,  g_Hh);
    cudaGetSymbolAddress((void**)&Gh,  g_Gh);
    cudaGetSymbolAddress((void**)&WPH, g_wpH);
    cudaGetSymbolAddress((void**)&WPL, g_wpL);

    cudaFuncSetAttribute(k_gemm_mma<0,0,1>, cudaFuncAttributeMaxDynamicSharedMemorySize, TC_SMEM);
    cudaFuncSetAttribute(k_gemm_mma<0,1,1>, cudaFuncAttributeMaxDynamicSharedMemorySize, TC_SMEM);
    cudaFuncSetAttribute(k_gemm_mma<1,1,0>, cudaFuncAttributeMaxDynamicSharedMemorySize, TC_SMEM);

    const int TB = 256;
    int gb_n   = (n + TB - 1) / TB;
    int gb_e   = (E + TB - 1) / TB;
    int ntiles = (n + 127) / 128;               // 128-row gemm tiles
    int gb_w   = ((n * 8) + TB - 1) / TB;       // gather blocks (8 thr/node)
    int nb     = (n + 255) / 256;               // scan blocks

    // 1..3: init / count / prep (W planes incl. Wm, BN folds, fb)
    k_init<<<gb_n, TB>>>((const unsigned int*)ei, n);
    k_count<<<gb_e, TB>>>(ei, E);
    k_prep<<<7, TB>>>(W1, W2, pW2, W3, pW1,
                      b1, bn1g, bn1b, bn1m, bn1v,
                      b2, bn2g, bn2b, bn2m, bn2v,
                      b3, pb1);

    // 4: GEMM1 (profiled launch) — fp32 x in, fp16 out
    k_gemm_mma<0,0,1><<<ntiles, TB, TC_SMEM>>>(x, WPH + 0, WPL + 0, nullptr, Hh, n);

    // 5..8: CSR build
    k_scan1<<<nb, 256>>>(n);
    k_scan2<<<1, 512>>>(nb);
    k_scan3<<<gb_n, TB>>>(n);
    k_fill<<<gb_e, TB>>>(ei, E);

    // layer 1 aggregation + BN1/ReLU (fp16 in/out)
    k_gather<1><<<gb_w, TB>>>(Hh, Gh, n);

    // layer 2
    k_gemm_mma<0,1,1><<<ntiles, TB, TC_SMEM>>>(Gh, WPH + 576, WPL + 576, nullptr, Hh, n);
    k_gather<2><<<gb_w, TB>>>(Hh, Gh, n);

    // layer 3 + predictor-GEMM1 merged: Gh = tanh(agg(Gh @ Wm) + fb)
    k_gemm_mma<0,1,1><<<ntiles, TB, TC_SMEM>>>(Gh, WPH + 1152, WPL + 1152, nullptr, Hh, n);
    k_gather<3><<<gb_w, TB>>>(Hh, Gh, n);

    // predictor output GEMM (fp16 in, fp32 out, +bias)
    k_gemm_mma<1,1,0><<<ntiles, TB, TC_SMEM>>>(Gh, WPH + 1728, WPL + 1728, pb2, out, n);
}

// round 16
// speedup vs baseline: 1.8425x; 1.0907x over previous
#include <cuda_runtime.h>
#include <cuda_bf16.h>
#include <cuda_fp16.h>
#include <math.h>
#include <stdint.h>

#define MAXN 100000
#define MAXE 800000
#define FD 64
#define BN_EPS 1e-5f

typedef unsigned long long ULL;

// ---------------- scratch (no allocations allowed) ----------------
__device__ int    g_cnt[MAXN];
__device__ int    g_off[MAXN + 1];
__device__ int    g_cursor[MAXN];
__device__ int    g_bsum[512];
__device__ float  g_dis[MAXN];
__device__ ULL    g_csr[MAXE];     // packed {src:int, norm:float}
__device__ __half g_Hh[(size_t)MAXN * FD];   // fp16 GEMM->gather intermediate
__device__ __half g_Gh[(size_t)MAXN * FD];   // fp16 gather->GEMM intermediate
// W fp16 hi/lo planes, layout [k][72] fp16 (=576 uint4); slots 0=W1,1=W2,2=Wm,3=pW2
__device__ uint4  g_wpH[4][576];
__device__ uint4  g_wpL[4][576];
__device__ float  g_scale1[FD], g_shift1[FD];
__device__ float  g_scale2[FD], g_shift2[FD];
__device__ float  g_fb[FD];
__device__ int    g_is64;

// ---------------- static side stream + fork/join events (host resources only,
// created once at load, reused deterministically every call) ----------------
static cudaStream_t g_s2;
static cudaEvent_t  g_evF, g_evJ;
namespace {
struct StreamInit {
    StreamInit() {
        cudaStreamCreateWithFlags(&g_s2, cudaStreamNonBlocking);
        cudaEventCreateWithFlags(&g_evF, cudaEventDisableTiming);
        cudaEventCreateWithFlags(&g_evJ, cudaEventDisableTiming);
    }
};
StreamInit g_si;
}

// ---------------- edge dtype detect ----------------
__global__ void k_detect(const unsigned int* ei) {
    if (threadIdx.x == 0) {
        int is64 = 1;
        for (int j = 1; j < 64; j += 2)
            if (ei[j] != 0u) { is64 = 0; break; }
        g_is64 = is64;
    }
}

__device__ __forceinline__ int load_idx(const void* ei, long long pos) {
    if (g_is64) return (int)((const long long*)ei)[pos];
    return ((const int*)ei)[pos];
}

__global__ void k_count(const void* ei, int E) {
    int e = blockIdx.x * blockDim.x + threadIdx.x;
    if (e >= E) return;
    int dst = load_idx(ei, (long long)E + e);
    atomicAdd(&g_cnt[dst], 1);
}

// ---------------- helpers ----------------
__device__ __forceinline__ uint32_t packh2(float a, float b) {
    __half2 h = __floats2half2_rn(a, b);
    return *(uint32_t*)&h;
}

// split one W into fp16 hi/lo planes [k][72], wide uint4 stores.
__device__ __forceinline__ void wsplit_one(const float* __restrict__ src, int slot,
                                           int tid) {
#pragma unroll
    for (int i = 0; i < 2; i++) {
        int t = tid + i * 256;          // 0..511
        int k = t >> 3, g = t & 7;
        uint32_t hi[4], lo[4];
#pragma unroll
        for (int p = 0; p < 4; p++) {
            float v0 = src[k * FD + g * 8 + 2 * p];
            float v1 = src[k * FD + g * 8 + 2 * p + 1];
            float h0 = __half2float(__float2half_rn(v0));
            float h1 = __half2float(__float2half_rn(v1));
            hi[p] = packh2(h0, h1);
            lo[p] = packh2(v0 - h0, v1 - h1);
        }
        ((uint4*)&g_wpH[slot][0])[k * 9 + g] = make_uint4(hi[0], hi[1], hi[2], hi[3]);
        ((uint4*)&g_wpL[slot][0])[k * 9 + g] = make_uint4(lo[0], lo[1], lo[2], lo[3]);
    }
}

// blocks 0-2: split W1/W2/pW2 ; 3-4: BN folds ; 5: fused bias ; 6: Wm=W3@pW1 + split
__global__ void k_prep(const float* W1, const float* W2, const float* pW2,
                       const float* W3, const float* pW1,
                       const float* b1, const float* g1, const float* bb1,
                       const float* m1, const float* v1,
                       const float* b2, const float* g2, const float* bb2,
                       const float* m2, const float* v2,
                       const float* b3, const float* pb1) {
    int bx = blockIdx.x;
    int tid = threadIdx.x;
    if (bx < 3) {
        const float* src = (bx == 0) ? W1 : (bx == 1) ? W2 : pW2;
        int slot = (bx == 2) ? 3 : bx;
        wsplit_one(src, slot, tid);
        return;
    }
    if (bx == 6) {
        __shared__ float Bs[FD * FD];
        __shared__ float Wm_s[FD * FD];
#pragma unroll
        for (int i = 0; i < 16; i++) Bs[tid + i * 256] = pW1[tid + i * 256];
        __syncthreads();
        int r = tid >> 2, c0 = (tid & 3) * 16;
        float acc[16];
#pragma unroll
        for (int j = 0; j < 16; j++) acc[j] = 0.f;
        for (int k = 0; k < FD; k++) {
            float a = W3[r * FD + k];
#pragma unroll
            for (int j = 0; j < 16; j++) acc[j] = fmaf(a, Bs[k * FD + c0 + j], acc[j]);
        }
#pragma unroll
        for (int j = 0; j < 16; j++) Wm_s[r * FD + c0 + j] = acc[j];
        __syncthreads();
        wsplit_one(Wm_s, 2, tid);
        return;
    }
    int c = tid;
    if (c >= FD) return;
    if (bx == 3) {
        float s = g1[c] * rsqrtf(v1[c] + BN_EPS);
        g_scale1[c] = s;
        g_shift1[c] = (b1[c] - m1[c]) * s + bb1[c];
    } else if (bx == 4) {
        float s = g2[c] * rsqrtf(v2[c] + BN_EPS);
        g_scale2[c] = s;
        g_shift2[c] = (b2[c] - m2[c]) * s + bb2[c];
    } else {
        float s = pb1[c];
        for (int k = 0; k < FD; k++) s += b3[k] * pW1[k * FD + c];
        g_fb[c] = s;
    }
}

// ---------------- scans ----------------
__global__ void k_scan1(int n) {
    __shared__ int s[256];
    int i = blockIdx.x * 256 + threadIdx.x;
    int v = (i < n) ? g_cnt[i] : 0;
    if (i < n) g_dis[i] = rsqrtf((float)(v + 1));   // +1 self loop
    s[threadIdx.x] = v;
    __syncthreads();
#pragma unroll
    for (int off = 1; off < 256; off <<= 1) {
        int t = (threadIdx.x >= off) ? s[threadIdx.x - off] : 0;
        __syncthreads();
        s[threadIdx.x] += t;
        __syncthreads();
    }
    if (i < n) g_off[i + 1] = s[threadIdx.x];
    if (threadIdx.x == 255) g_bsum[blockIdx.x] = s[255];
}

__global__ void k_scan2(int nb) {
    __shared__ int s[512];
    int t = threadIdx.x;
    int v = (t < nb) ? g_bsum[t] : 0;
    s[t] = v;
    __syncthreads();
#pragma unroll
    for (int off = 1; off < 512; off <<= 1) {
        int u = (t >= off) ? s[t - off] : 0;
        __syncthreads();
        s[t] += u;
        __syncthreads();
    }
    if (t < nb) g_bsum[t] = s[t] - v;   // exclusive
}

__global__ void k_scan3(int n) {
    int i = blockIdx.x * blockDim.x + threadIdx.x;
    if (i < n) {
        int off = g_off[i + 1] + g_bsum[i >> 8];
        g_off[i + 1] = off;
        g_cursor[i] = off - g_cnt[i];
    }
    if (i == 0) g_off[0] = 0;
}

__global__ void k_fill(const void* ei, int E) {
    int e = blockIdx.x * blockDim.x + threadIdx.x;
    if (e >= E) return;
    int s = load_idx(ei, e);
    int d = load_idx(ei, (long long)E + e);
    float norm = g_dis[s] * g_dis[d];
    int pos = atomicAdd(&g_cursor[d], 1);
    g_csr[pos] = (ULL)(unsigned int)s | ((ULL)__float_as_uint(norm) << 32);
}

// ================= tensor-core GEMM (HMMA fp16, W split hi/lo) =================
// Y[n,64] = X[n,64] @ W[64,64] (+epilogue). One 128-row tile per block, 256 thr.
// A = fp16 activations used verbatim (1 plane); W = Wh + Wl fp16 planes.
// D = A*Wh + A*Wl fp32 via mma.m16n8k16.f32.f16.f16.f32 (2 MMAs per step).
// INH: 1 = X fp16 (pure copy), 0 = X fp32 (convert). OUTH: 1 = fp16 out.
// EPI: 0 = none, 1 = +bias.

#define LDA 72
#define OFF_WHI (128 * LDA * 2)           // 18432
#define WPLANE  (64 * LDA * 2)            // 9216
#define OFF_WLO (OFF_WHI + WPLANE)
#define TC_SMEM (OFF_WHI + 2 * WPLANE)    // 36864

__device__ __forceinline__ uint32_t smem_u32(const void* p) {
    uint32_t a;
    asm("{ .reg .u64 t; cvta.to.shared.u64 t, %1; cvt.u32.u64 %0, t; }"
        : "=r"(a) : "l"(p));
    return a;
}
__device__ __forceinline__ void ldmA(uint32_t addr, uint32_t r[4]) {
    asm volatile("ldmatrix.sync.aligned.m8n8.x4.shared.b16 {%0,%1,%2,%3}, [%4];"
                 : "=r"(r[0]), "=r"(r[1]), "=r"(r[2]), "=r"(r[3]) : "r"(addr));
}
__device__ __forceinline__ void ldmBT(uint32_t addr, uint32_t r[4]) {
    asm volatile("ldmatrix.sync.aligned.m8n8.x4.trans.shared.b16 {%0,%1,%2,%3}, [%4];"
                 : "=r"(r[0]), "=r"(r[1]), "=r"(r[2]), "=r"(r[3]) : "r"(addr));
}
__device__ __forceinline__ void hmma16(float d[4], const uint32_t a[4],
                                       uint32_t b0, uint32_t b1) {
    asm volatile(
        "mma.sync.aligned.m16n8k16.row.col.f32.f16.f16.f32 "
        "{%0,%1,%2,%3}, {%4,%5,%6,%7}, {%8,%9}, {%0,%1,%2,%3};"
        : "+f"(d[0]), "+f"(d[1]), "+f"(d[2]), "+f"(d[3])
        : "r"(a[0]), "r"(a[1]), "r"(a[2]), "r"(a[3]), "r"(b0), "r"(b1));
}

template <int EPI, int INH, int OUTH>
__global__ void __launch_bounds__(256)
k_gemm_mma(const void* __restrict__ Xv,
           const uint4* __restrict__ whp, const uint4* __restrict__ wlp,
           const float* __restrict__ bias, void* __restrict__ Yv, int n) {
    extern __shared__ char smem[];
    uint32_t sb = smem_u32(smem);
    int tid = threadIdx.x, w = tid >> 5, lane = tid & 31;
    int row0 = blockIdx.x * 128;

    // ---- W planes: coalesced uint4 copy (576 each) ----
#pragma unroll
    for (int i = 0; i < 3; i++) {
        int idx = tid + i * 256;
        if (idx < 576) {
            ((uint4*)(smem + OFF_WHI))[idx] = whp[idx];
            ((uint4*)(smem + OFF_WLO))[idx] = wlp[idx];
        }
    }
    // ---- A tile -> smem [r][k] fp16 (1024 uint4-groups, 4/thread) ----
#pragma unroll
    for (int i = 0; i < 4; i++) {
        int t = tid + i * 256;
        int r = t >> 3, g = t & 7;
        int row = row0 + r;
        uint4 v = make_uint4(0u, 0u, 0u, 0u);
        if (row < n) {
            if (INH) {
                v = ((const uint4*)Xv)[(size_t)row * 8 + g];
            } else {
                const float4* xp = (const float4*)((const float*)Xv + (size_t)row * FD + g * 8);
                float4 a = xp[0], b = xp[1];
                v.x = packh2(a.x, a.y);
                v.y = packh2(a.z, a.w);
                v.z = packh2(b.x, b.y);
                v.w = packh2(b.z, b.w);
            }
        }
        *(uint4*)(smem + r * (LDA * 2) + g * 16) = v;
    }
    __syncthreads();

    uint32_t aA = sb + ((w * 16 + (lane & 15)) * LDA + (lane >> 4) * 8) * 2;
    uint32_t aB = sb + OFF_WHI + ((lane & 15) * LDA + (lane >> 4) * 8) * 2;
    uint32_t aBl = aB + WPLANE;

    float acc[8][4];
#pragma unroll
    for (int i = 0; i < 8; i++)
#pragma unroll
        for (int j = 0; j < 4; j++) acc[i][j] = 0.f;

#pragma unroll
    for (int ks = 0; ks < 4; ks++) {
        uint32_t ah[4];
        ldmA(aA + ks * 32, ah);            // +16 fp16 cols per k-step
        uint32_t krow = ks * 16 * LDA * 2;
#pragma unroll
        for (int pr = 0; pr < 4; pr++) {   // ntile pair: cols pr*16 .. pr*16+15
            uint32_t bh[4], bl[4];
            ldmBT(aB + krow + pr * 32, bh);
            ldmBT(aBl + krow + pr * 32, bl);
            int nt = pr * 2;
            hmma16(acc[nt],     ah, bh[0], bh[1]);
            hmma16(acc[nt],     ah, bl[0], bl[1]);
            hmma16(acc[nt + 1], ah, bh[2], bh[3]);
            hmma16(acc[nt + 1], ah, bl[2], bl[3]);
        }
    }

    // epilogue: {c0,c1} at (lane/4, 2*(lane%4)), {c2,c3} at row+8
    int r0 = row0 + w * 16 + (lane >> 2);
    int cbase = (lane & 3) * 2;
#pragma unroll
    for (int half = 0; half < 2; half++) {
        int row = r0 + half * 8;
        if (row >= n) continue;
#pragma unroll
        for (int nt = 0; nt < 8; nt++) {
            int c = nt * 8 + cbase;
            float2 v = make_float2(acc[nt][2 * half], acc[nt][2 * half + 1]);
            if (EPI == 1) { v.x += bias[c]; v.y += bias[c + 1]; }
            if (OUTH) {
                __half* yr = ((__half*)Yv) + (size_t)row * FD;
                *(__half2*)(yr + c) = __floats2half2_rn(v.x, v.y);
            } else {
                float* yr = ((float*)Yv) + (size_t)row * FD;
                *(float2*)(yr + c) = v;
            }
        }
    }
}

// ---------------- gather aggregation (CSR), fp16 in, fp16 out, 8 lanes/node -----
// 4 nodes per warp -> 4 independent load chains. Lane group g = lane&7 covers
// cols [8g..8g+7] (one uint4 = 8 halves; 8 lanes x 16B = 128B = full row).
// EPI: 1 = BN1+ReLU, 2 = BN2+ReLU, 3 = tanh(. + fb)
__device__ __forceinline__ void cvt8(uint4 v, float f[8]) {
    float2 a = __half22float2(*(__half2*)&v.x);
    float2 b = __half22float2(*(__half2*)&v.y);
    float2 c = __half22float2(*(__half2*)&v.z);
    float2 d = __half22float2(*(__half2*)&v.w);
    f[0] = a.x; f[1] = a.y; f[2] = b.x; f[3] = b.y;
    f[4] = c.x; f[5] = c.y; f[6] = d.x; f[7] = d.y;
}

template <int EPI>
__global__ void __launch_bounds__(256)
k_gather(const __half* __restrict__ h, __half* __restrict__ out, int n) {
    int t = blockIdx.x * blockDim.x + threadIdx.x;
    int node = t >> 3;              // 8 threads per node
    int g = threadIdx.x & 7;        // col chunk [8g..8g+7]
    if (node >= n) return;

    const uint4* hp = (const uint4*)h;   // row = 8 uint4
    float d = g_dis[node];
    float s2 = d * d;

    float acc[8];
    cvt8(hp[(size_t)node * 8 + g], acc);
#pragma unroll
    for (int j = 0; j < 8; j++) acc[j] *= s2;

    int e = g_off[node], end = g_off[node + 1];

    for (; e + 2 <= end; e += 2) {
        ULL e0 = g_csr[e];
        ULL e1 = g_csr[e + 1];
        uint4 r0 = hp[(size_t)(unsigned)e0 * 8 + g];
        uint4 r1 = hp[(size_t)(unsigned)e1 * 8 + g];
        float n0 = __uint_as_float((unsigned)(e0 >> 32));
        float n1 = __uint_as_float((unsigned)(e1 >> 32));
        float f0[8], f1[8];
        cvt8(r0, f0); cvt8(r1, f1);
#pragma unroll
        for (int j = 0; j < 8; j++) acc[j] = fmaf(f0[j], n0, acc[j]);
#pragma unroll
        for (int j = 0; j < 8; j++) acc[j] = fmaf(f1[j], n1, acc[j]);
    }
    if (e < end) {
        ULL e0 = g_csr[e];
        uint4 r0 = hp[(size_t)(unsigned)e0 * 8 + g];
        float n0 = __uint_as_float((unsigned)(e0 >> 32));
        float f0[8];
        cvt8(r0, f0);
#pragma unroll
        for (int j = 0; j < 8; j++) acc[j] = fmaf(f0[j], n0, acc[j]);
    }

    int c0 = g * 8;
    if (EPI == 1) {
#pragma unroll
        for (int j = 0; j < 8; j++)
            acc[j] = fmaxf(fmaf(acc[j], g_scale1[c0 + j], g_shift1[c0 + j]), 0.f);
    } else if (EPI == 2) {
#pragma unroll
        for (int j = 0; j < 8; j++)
            acc[j] = fmaxf(fmaf(acc[j], g_scale2[c0 + j], g_shift2[c0 + j]), 0.f);
    } else if (EPI == 3) {
#pragma unroll
        for (int j = 0; j < 8; j++)
            acc[j] = tanhf(acc[j] + g_fb[c0 + j]);
    }
    uint4 st;
    st.x = packh2(acc[0], acc[1]);
    st.y = packh2(acc[2], acc[3]);
    st.z = packh2(acc[4], acc[5]);
    st.w = packh2(acc[6], acc[7]);
    ((uint4*)out)[(size_t)node * 8 + g] = st;
}

// ---------------- launch ----------------
extern "C" void kernel_launch(void* const* d_in, const int* in_sizes, int n_in,
                              void* d_out, int out_size) {
    const float* x    = (const float*)d_in[0];
    const void*  ei   = d_in[1];
    const float* W1   = (const float*)d_in[2];
    const float* b1   = (const float*)d_in[3];
    const float* W2   = (const float*)d_in[4];
    const float* b2   = (const float*)d_in[5];
    const float* W3   = (const float*)d_in[6];
    const float* b3   = (const float*)d_in[7];
    const float* bn1g = (const float*)d_in[8];
    const float* bn1b = (const float*)d_in[9];
    const float* bn1m = (const float*)d_in[10];
    const float* bn1v = (const float*)d_in[11];
    const float* bn2g = (const float*)d_in[12];
    const float* bn2b = (const float*)d_in[13];
    const float* bn2m = (const float*)d_in[14];
    const float* bn2v = (const float*)d_in[15];
    const float* pW1  = (const float*)d_in[16];
    const float* pb1  = (const float*)d_in[17];
    const float* pW2  = (const float*)d_in[18];
    const float* pb2  = (const float*)d_in[19];
    float* out = (float*)d_out;

    int n = in_sizes[0] / FD;
    int E = in_sizes[1] / 2;
    if (n > MAXN) n = MAXN;
    if (E > MAXE) E = MAXE;

    __half *Hh, *Gh;
    uint4 *WPH, *WPL;
    int* CNT;
    cudaGetSymbolAddress((void**)&Hh,  g_Hh);
    cudaGetSymbolAddress((void**)&Gh,  g_Gh);
    cudaGetSymbolAddress((void**)&WPH, g_wpH);
    cudaGetSymbolAddress((void**)&WPL, g_wpL);
    cudaGetSymbolAddress((void**)&CNT, g_cnt);

    cudaFuncSetAttribute(k_gemm_mma<0,0,1>, cudaFuncAttributeMaxDynamicSharedMemorySize, TC_SMEM);
    cudaFuncSetAttribute(k_gemm_mma<0,1,1>, cudaFuncAttributeMaxDynamicSharedMemorySize, TC_SMEM);
    cudaFuncSetAttribute(k_gemm_mma<1,1,0>, cudaFuncAttributeMaxDynamicSharedMemorySize, TC_SMEM);

    const int TB = 256;
    int gb_n   = (n + TB - 1) / TB;
    int gb_e   = (E + TB - 1) / TB;
    int ntiles = (n + 127) / 128;               // 128-row gemm tiles
    int gb_w   = ((n * 8) + TB - 1) / TB;       // gather blocks (8 thr/node)
    int nb     = (n + 255) / 256;               // scan blocks

    // ---- fork: side stream runs prep + GEMM1 (independent of CSR) ----
    cudaEventRecord(g_evF, 0);
    cudaStreamWaitEvent(g_s2, g_evF, 0);

    k_prep<<<7, TB, 0, g_s2>>>(W1, W2, pW2, W3, pW1,
                               b1, bn1g, bn1b, bn1m, bn1v,
                               b2, bn2g, bn2b, bn2m, bn2v,
                               b3, pb1);
    k_gemm_mma<0,0,1><<<ntiles, TB, TC_SMEM, g_s2>>>(x, WPH + 0, WPL + 0,
                                                     nullptr, Hh, n);
    cudaEventRecord(g_evJ, g_s2);

    // ---- main stream: CSR build ----
    cudaMemsetAsync(CNT, 0, (size_t)n * sizeof(int));
    k_detect<<<1, 32>>>((const unsigned int*)ei);
    k_count<<<gb_e, TB>>>(ei, E);
    k_scan1<<<nb, 256>>>(n);
    k_scan2<<<1, 512>>>(nb);
    k_scan3<<<gb_n, TB>>>(n);
    k_fill<<<gb_e, TB>>>(ei, E);

    // ---- join: gather-1 needs Hh (side) + CSR + BN consts ----
    cudaStreamWaitEvent(0, g_evJ, 0);

    // layer 1 aggregation + BN1/ReLU (fp16 in/out)
    k_gather<1><<<gb_w, TB>>>(Hh, Gh, n);

    // layer 2
    k_gemm_mma<0,1,1><<<ntiles, TB, TC_SMEM>>>(Gh, WPH + 576, WPL + 576, nullptr, Hh, n);
    k_gather<2><<<gb_w, TB>>>(Hh, Gh, n);

    // layer 3 + predictor-GEMM1 merged: Gh = tanh(agg(Gh @ Wm) + fb)
    k_gemm_mma<0,1,1><<<ntiles, TB, TC_SMEM>>>(Gh, WPH + 1152, WPL + 1152, nullptr, Hh, n);
    k_gather<3><<<gb_w, TB>>>(Hh, Gh, n);

    // predictor output GEMM (fp16 in, fp32 out, +bias)
    k_gemm_mma<1,1,0><<<ntiles, TB, TC_SMEM>>>(Gh, WPH + 1728, WPL + 1728, pb2, out, n);
}

// round 17
// speedup vs baseline: 1.8546x; 1.0065x over previous
#include <cuda_runtime.h>
#include <cuda_bf16.h>
#include <cuda_fp16.h>
#include <math.h>
#include <stdint.h>

#define MAXN 100000
#define MAXE 800000
#define FD 64
#define BN_EPS 1e-5f

typedef unsigned long long ULL;

// ---------------- scratch (no allocations allowed) ----------------
__device__ int    g_cnt[MAXN];
__device__ int    g_off[MAXN + 1];
__device__ int    g_cursor[MAXN];
__device__ int    g_bsum[512];
__device__ float  g_dis[MAXN];
__device__ ULL    g_csr[MAXE];     // packed {src:int, norm:float}
__device__ __half g_Hh[(size_t)MAXN * FD];   // fp16 GEMM->gather intermediate
__device__ __half g_Gh[(size_t)MAXN * FD];   // fp16 gather->GEMM intermediate
// W fp16 hi/lo planes, layout [k][72] fp16 (=576 uint4); slots 0=W1,1=W2,2=Wm,3=pW2
__device__ uint4  g_wpH[4][576];
__device__ uint4  g_wpL[4][576];
__device__ float  g_scale1[FD], g_shift1[FD];
__device__ float  g_scale2[FD], g_shift2[FD];
__device__ float  g_fb[FD];
__device__ int    g_is64;

// ---------------- static side stream + fork/join events ----------------
static cudaStream_t g_s2;
static cudaEvent_t  g_evF, g_evJ;
namespace {
struct StreamInit {
    StreamInit() {
        cudaStreamCreateWithFlags(&g_s2, cudaStreamNonBlocking);
        cudaEventCreateWithFlags(&g_evF, cudaEventDisableTiming);
        cudaEventCreateWithFlags(&g_evJ, cudaEventDisableTiming);
    }
};
StreamInit g_si;
}

// ---------------- edge dtype detect ----------------
__global__ void k_detect(const unsigned int* ei) {
    if (threadIdx.x == 0) {
        int is64 = 1;
        for (int j = 1; j < 64; j += 2)
            if (ei[j] != 0u) { is64 = 0; break; }
        g_is64 = is64;
    }
}

// low-32-bit index load (values < 2^31, little-endian)
__device__ __forceinline__ int load_idx32(const void* ei, long long pos) {
    if (g_is64) return ((const int*)ei)[2 * pos];
    return ((const int*)ei)[pos];
}

__global__ void k_count(const void* ei, int E) {
    int e = blockIdx.x * blockDim.x + threadIdx.x;
    if (e >= E) return;
    int dst = load_idx32(ei, (long long)E + e);
    atomicAdd(&g_cnt[dst], 1);
}

// ---------------- helpers ----------------
__device__ __forceinline__ uint32_t packh2(float a, float b) {
    __half2 h = __floats2half2_rn(a, b);
    return *(uint32_t*)&h;
}

// split one W into fp16 hi/lo planes [k][72], wide uint4 stores.
__device__ __forceinline__ void wsplit_one(const float* __restrict__ src, int slot,
                                           int tid) {
#pragma unroll
    for (int i = 0; i < 2; i++) {
        int t = tid + i * 256;          // 0..511
        int k = t >> 3, g = t & 7;
        uint32_t hi[4], lo[4];
#pragma unroll
        for (int p = 0; p < 4; p++) {
            float v0 = src[k * FD + g * 8 + 2 * p];
            float v1 = src[k * FD + g * 8 + 2 * p + 1];
            float h0 = __half2float(__float2half_rn(v0));
            float h1 = __half2float(__float2half_rn(v1));
            hi[p] = packh2(h0, h1);
            lo[p] = packh2(v0 - h0, v1 - h1);
        }
        ((uint4*)&g_wpH[slot][0])[k * 9 + g] = make_uint4(hi[0], hi[1], hi[2], hi[3]);
        ((uint4*)&g_wpL[slot][0])[k * 9 + g] = make_uint4(lo[0], lo[1], lo[2], lo[3]);
    }
}

// blocks 0-2: split W1/W2/pW2 ; 3-4: BN folds ; 5: fused bias ; 6: Wm=W3@pW1 + split
__global__ void k_prep(const float* W1, const float* W2, const float* pW2,
                       const float* W3, const float* pW1,
                       const float* b1, const float* g1, const float* bb1,
                       const float* m1, const float* v1,
                       const float* b2, const float* g2, const float* bb2,
                       const float* m2, const float* v2,
                       const float* b3, const float* pb1) {
    int bx = blockIdx.x;
    int tid = threadIdx.x;
    if (bx < 3) {
        const float* src = (bx == 0) ? W1 : (bx == 1) ? W2 : pW2;
        int slot = (bx == 2) ? 3 : bx;
        wsplit_one(src, slot, tid);
        return;
    }
    if (bx == 6) {
        __shared__ float Bs[FD * FD];
        __shared__ float Wm_s[FD * FD];
#pragma unroll
        for (int i = 0; i < 16; i++) Bs[tid + i * 256] = pW1[tid + i * 256];
        __syncthreads();
        int r = tid >> 2, c0 = (tid & 3) * 16;
        float acc[16];
#pragma unroll
        for (int j = 0; j < 16; j++) acc[j] = 0.f;
        for (int k = 0; k < FD; k++) {
            float a = W3[r * FD + k];
#pragma unroll
            for (int j = 0; j < 16; j++) acc[j] = fmaf(a, Bs[k * FD + c0 + j], acc[j]);
        }
#pragma unroll
        for (int j = 0; j < 16; j++) Wm_s[r * FD + c0 + j] = acc[j];
        __syncthreads();
        wsplit_one(Wm_s, 2, tid);
        return;
    }
    int c = tid;
    if (c >= FD) return;
    if (bx == 3) {
        float s = g1[c] * rsqrtf(v1[c] + BN_EPS);
        g_scale1[c] = s;
        g_shift1[c] = (b1[c] - m1[c]) * s + bb1[c];
    } else if (bx == 4) {
        float s = g2[c] * rsqrtf(v2[c] + BN_EPS);
        g_scale2[c] = s;
        g_shift2[c] = (b2[c] - m2[c]) * s + bb2[c];
    } else {
        float s = pb1[c];
        for (int k = 0; k < FD; k++) s += b3[k] * pW1[k * FD + c];
        g_fb[c] = s;
    }
}

// ---------------- scans ----------------
// scan1: per-256-block inclusive prefix; g_off[i+1] = in-block inclusive, bsum.
__global__ void k_scan1(int n) {
    __shared__ int s[256];
    int i = blockIdx.x * 256 + threadIdx.x;
    int v = (i < n) ? g_cnt[i] : 0;
    if (i < n) g_dis[i] = rsqrtf((float)(v + 1));   // +1 self loop
    s[threadIdx.x] = v;
    __syncthreads();
#pragma unroll
    for (int off = 1; off < 256; off <<= 1) {
        int t = (threadIdx.x >= off) ? s[threadIdx.x - off] : 0;
        __syncthreads();
        s[threadIdx.x] += t;
        __syncthreads();
    }
    if (i < n) g_off[i + 1] = s[threadIdx.x];
    if (threadIdx.x == 255) g_bsum[blockIdx.x] = s[255];
}

// scan3 (absorbs scan2): each 512-thread block redundantly scans bsum in smem,
// then finalizes offsets + cursors for 512 nodes.
__global__ void __launch_bounds__(512)
k_scan3(int n, int nb) {
    __shared__ int s[512];
    __shared__ int o[512];
    int t = threadIdx.x;
    int v = (t < nb) ? g_bsum[t] : 0;
    s[t] = v; o[t] = v;
    __syncthreads();
#pragma unroll
    for (int off = 1; off < 512; off <<= 1) {
        int u = (t >= off) ? s[t - off] : 0;
        __syncthreads();
        s[t] += u;
        __syncthreads();
    }
    // exclusive prefix of bsum: s[b] - o[b]
    int i = blockIdx.x * 512 + t;
    if (i < n) {
        int b = i >> 8;
        int off = g_off[i + 1] + (s[b] - o[b]);
        g_off[i + 1] = off;
        g_cursor[i] = off - g_cnt[i];
    }
    if (i == 0) g_off[0] = 0;
}

__global__ void k_fill(const void* ei, int E) {
    int e = blockIdx.x * blockDim.x + threadIdx.x;
    if (e >= E) return;
    int s = load_idx32(ei, e);
    int d = load_idx32(ei, (long long)E + e);
    float norm = g_dis[s] * g_dis[d];
    int pos = atomicAdd(&g_cursor[d], 1);
    g_csr[pos] = (ULL)(unsigned int)s | ((ULL)__float_as_uint(norm) << 32);
}

// ================= tensor-core GEMM (HMMA fp16, W split hi/lo) =================
// Y[n,64] = X[n,64] @ W[64,64] (+epilogue). One 128-row tile per block, 256 thr.
// A = fp16 activations verbatim; W = Wh + Wl fp16 planes.
// D = A*Wh + A*Wl fp32 via mma.m16n8k16.f32.f16.f16.f32.
// INH: 1 = X fp16 (pure copy), 0 = X fp32 (convert). OUTH: 1 = fp16 out.
// EPI: 0 = none, 1 = +bias.

#define LDA 72
#define OFF_WHI (128 * LDA * 2)           // 18432
#define WPLANE  (64 * LDA * 2)            // 9216
#define OFF_WLO (OFF_WHI + WPLANE)
#define TC_SMEM (OFF_WHI + 2 * WPLANE)    // 36864

__device__ __forceinline__ uint32_t smem_u32(const void* p) {
    uint32_t a;
    asm("{ .reg .u64 t; cvta.to.shared.u64 t, %1; cvt.u32.u64 %0, t; }"
        : "=r"(a) : "l"(p));
    return a;
}
__device__ __forceinline__ void ldmA(uint32_t addr, uint32_t r[4]) {
    asm volatile("ldmatrix.sync.aligned.m8n8.x4.shared.b16 {%0,%1,%2,%3}, [%4];"
                 : "=r"(r[0]), "=r"(r[1]), "=r"(r[2]), "=r"(r[3]) : "r"(addr));
}
__device__ __forceinline__ void ldmBT(uint32_t addr, uint32_t r[4]) {
    asm volatile("ldmatrix.sync.aligned.m8n8.x4.trans.shared.b16 {%0,%1,%2,%3}, [%4];"
                 : "=r"(r[0]), "=r"(r[1]), "=r"(r[2]), "=r"(r[3]) : "r"(addr));
}
__device__ __forceinline__ void hmma16(float d[4], const uint32_t a[4],
                                       uint32_t b0, uint32_t b1) {
    asm volatile(
        "mma.sync.aligned.m16n8k16.row.col.f32.f16.f16.f32 "
        "{%0,%1,%2,%3}, {%4,%5,%6,%7}, {%8,%9}, {%0,%1,%2,%3};"
        : "+f"(d[0]), "+f"(d[1]), "+f"(d[2]), "+f"(d[3])
        : "r"(a[0]), "r"(a[1]), "r"(a[2]), "r"(a[3]), "r"(b0), "r"(b1));
}

template <int EPI, int INH, int OUTH>
__global__ void __launch_bounds__(256)
k_gemm_mma(const void* __restrict__ Xv,
           const uint4* __restrict__ whp, const uint4* __restrict__ wlp,
           const float* __restrict__ bias, void* __restrict__ Yv, int n) {
    extern __shared__ char smem[];
    uint32_t sb = smem_u32(smem);
    int tid = threadIdx.x, w = tid >> 5, lane = tid & 31;
    int row0 = blockIdx.x * 128;

    // ---- W planes: coalesced uint4 copy (576 each) ----
#pragma unroll
    for (int i = 0; i < 3; i++) {
        int idx = tid + i * 256;
        if (idx < 576) {
            ((uint4*)(smem + OFF_WHI))[idx] = whp[idx];
            ((uint4*)(smem + OFF_WLO))[idx] = wlp[idx];
        }
    }
    // ---- A tile -> smem [r][k] fp16 ----
#pragma unroll
    for (int i = 0; i < 4; i++) {
        int t = tid + i * 256;
        int r = t >> 3, g = t & 7;
        int row = row0 + r;
        uint4 v = make_uint4(0u, 0u, 0u, 0u);
        if (row < n) {
            if (INH) {
                v = ((const uint4*)Xv)[(size_t)row * 8 + g];
            } else {
                const float4* xp = (const float4*)((const float*)Xv + (size_t)row * FD + g * 8);
                float4 a = xp[0], b = xp[1];
                v.x = packh2(a.x, a.y);
                v.y = packh2(a.z, a.w);
                v.z = packh2(b.x, b.y);
                v.w = packh2(b.z, b.w);
            }
        }
        *(uint4*)(smem + r * (LDA * 2) + g * 16) = v;
    }
    __syncthreads();

    uint32_t aA = sb + ((w * 16 + (lane & 15)) * LDA + (lane >> 4) * 8) * 2;
    uint32_t aB = sb + OFF_WHI + ((lane & 15) * LDA + (lane >> 4) * 8) * 2;
    uint32_t aBl = aB + WPLANE;

    float acc[8][4];
#pragma unroll
    for (int i = 0; i < 8; i++)
#pragma unroll
        for (int j = 0; j < 4; j++) acc[i][j] = 0.f;

#pragma unroll
    for (int ks = 0; ks < 4; ks++) {
        uint32_t ah[4];
        ldmA(aA + ks * 32, ah);
        uint32_t krow = ks * 16 * LDA * 2;
#pragma unroll
        for (int pr = 0; pr < 4; pr++) {
            uint32_t bh[4], bl[4];
            ldmBT(aB + krow + pr * 32, bh);
            ldmBT(aBl + krow + pr * 32, bl);
            int nt = pr * 2;
            hmma16(acc[nt],     ah, bh[0], bh[1]);
            hmma16(acc[nt],     ah, bl[0], bl[1]);
            hmma16(acc[nt + 1], ah, bh[2], bh[3]);
            hmma16(acc[nt + 1], ah, bl[2], bl[3]);
        }
    }

    int r0 = row0 + w * 16 + (lane >> 2);
    int cbase = (lane & 3) * 2;
#pragma unroll
    for (int half = 0; half < 2; half++) {
        int row = r0 + half * 8;
        if (row >= n) continue;
#pragma unroll
        for (int nt = 0; nt < 8; nt++) {
            int c = nt * 8 + cbase;
            float2 v = make_float2(acc[nt][2 * half], acc[nt][2 * half + 1]);
            if (EPI == 1) { v.x += bias[c]; v.y += bias[c + 1]; }
            if (OUTH) {
                __half* yr = ((__half*)Yv) + (size_t)row * FD;
                *(__half2*)(yr + c) = __floats2half2_rn(v.x, v.y);
            } else {
                float* yr = ((float*)Yv) + (size_t)row * FD;
                *(float2*)(yr + c) = v;
            }
        }
    }
}

// ---------------- gather aggregation (CSR), fp16 in/out, 8 lanes/node -----------
// 4 nodes per warp, 4-edge unroll per chain -> 16 outstanding loads/warp.
// EPI: 1 = BN1+ReLU, 2 = BN2+ReLU, 3 = tanh(. + fb)
__device__ __forceinline__ void cvt8(uint4 v, float f[8]) {
    float2 a = __half22float2(*(__half2*)&v.x);
    float2 b = __half22float2(*(__half2*)&v.y);
    float2 c = __half22float2(*(__half2*)&v.z);
    float2 d = __half22float2(*(__half2*)&v.w);
    f[0] = a.x; f[1] = a.y; f[2] = b.x; f[3] = b.y;
    f[4] = c.x; f[5] = c.y; f[6] = d.x; f[7] = d.y;
}

template <int EPI>
__global__ void __launch_bounds__(256)
k_gather(const __half* __restrict__ h, __half* __restrict__ out, int n) {
    int t = blockIdx.x * blockDim.x + threadIdx.x;
    int node = t >> 3;              // 8 threads per node
    int g = threadIdx.x & 7;        // col chunk [8g..8g+7]
    if (node >= n) return;

    const uint4* hp = (const uint4*)h;   // row = 8 uint4
    float d = g_dis[node];
    float s2 = d * d;

    float acc[8];
    cvt8(hp[(size_t)node * 8 + g], acc);
#pragma unroll
    for (int j = 0; j < 8; j++) acc[j] *= s2;

    int e = g_off[node], end = g_off[node + 1];

    for (; e + 4 <= end; e += 4) {
        ULL e0 = g_csr[e];
        ULL e1 = g_csr[e + 1];
        ULL e2 = g_csr[e + 2];
        ULL e3 = g_csr[e + 3];
        uint4 r0 = hp[(size_t)(unsigned)e0 * 8 + g];
        uint4 r1 = hp[(size_t)(unsigned)e1 * 8 + g];
        uint4 r2 = hp[(size_t)(unsigned)e2 * 8 + g];
        uint4 r3 = hp[(size_t)(unsigned)e3 * 8 + g];
        float n0 = __uint_as_float((unsigned)(e0 >> 32));
        float n1 = __uint_as_float((unsigned)(e1 >> 32));
        float n2 = __uint_as_float((unsigned)(e2 >> 32));
        float n3 = __uint_as_float((unsigned)(e3 >> 32));
        float f0[8], f1[8], f2[8], f3[8];
        cvt8(r0, f0); cvt8(r1, f1); cvt8(r2, f2); cvt8(r3, f3);
#pragma unroll
        for (int j = 0; j < 8; j++) acc[j] = fmaf(f0[j], n0, acc[j]);
#pragma unroll
        for (int j = 0; j < 8; j++) acc[j] = fmaf(f1[j], n1, acc[j]);
#pragma unroll
        for (int j = 0; j < 8; j++) acc[j] = fmaf(f2[j], n2, acc[j]);
#pragma unroll
        for (int j = 0; j < 8; j++) acc[j] = fmaf(f3[j], n3, acc[j]);
    }
    for (; e < end; e++) {
        ULL e0 = g_csr[e];
        uint4 r0 = hp[(size_t)(unsigned)e0 * 8 + g];
        float n0 = __uint_as_float((unsigned)(e0 >> 32));
        float f0[8];
        cvt8(r0, f0);
#pragma unroll
        for (int j = 0; j < 8; j++) acc[j] = fmaf(f0[j], n0, acc[j]);
    }

    int c0 = g * 8;
    if (EPI == 1) {
#pragma unroll
        for (int j = 0; j < 8; j++)
            acc[j] = fmaxf(fmaf(acc[j], g_scale1[c0 + j], g_shift1[c0 + j]), 0.f);
    } else if (EPI == 2) {
#pragma unroll
        for (int j = 0; j < 8; j++)
            acc[j] = fmaxf(fmaf(acc[j], g_scale2[c0 + j], g_shift2[c0 + j]), 0.f);
    } else if (EPI == 3) {
#pragma unroll
        for (int j = 0; j < 8; j++)
            acc[j] = tanhf(acc[j] + g_fb[c0 + j]);
    }
    uint4 st;
    st.x = packh2(acc[0], acc[1]);
    st.y = packh2(acc[2], acc[3]);
    st.z = packh2(acc[4], acc[5]);
    st.w = packh2(acc[6], acc[7]);
    ((uint4*)out)[(size_t)node * 8 + g] = st;
}

// ---------------- launch ----------------
extern "C" void kernel_launch(void* const* d_in, const int* in_sizes, int n_in,
                              void* d_out, int out_size) {
    const float* x    = (const float*)d_in[0];
    const void*  ei   = d_in[1];
    const float* W1   = (const float*)d_in[2];
    const float* b1   = (const float*)d_in[3];
    const float* W2   = (const float*)d_in[4];
    const float* b2   = (const float*)d_in[5];
    const float* W3   = (const float*)d_in[6];
    const float* b3   = (const float*)d_in[7];
    const float* bn1g = (const float*)d_in[8];
    const float* bn1b = (const float*)d_in[9];
    const float* bn1m = (const float*)d_in[10];
    const float* bn1v = (const float*)d_in[11];
    const float* bn2g = (const float*)d_in[12];
    const float* bn2b = (const float*)d_in[13];
    const float* bn2m = (const float*)d_in[14];
    const float* bn2v = (const float*)d_in[15];
    const float* pW1  = (const float*)d_in[16];
    const float* pb1  = (const float*)d_in[17];
    const float* pW2  = (const float*)d_in[18];
    const float* pb2  = (const float*)d_in[19];
    float* out = (float*)d_out;

    int n = in_sizes[0] / FD;
    int E = in_sizes[1] / 2;
    if (n > MAXN) n = MAXN;
    if (E > MAXE) E = MAXE;

    __half *Hh, *Gh;
    uint4 *WPH, *WPL;
    int* CNT;
    cudaGetSymbolAddress((void**)&Hh,  g_Hh);
    cudaGetSymbolAddress((void**)&Gh,  g_Gh);
    cudaGetSymbolAddress((void**)&WPH, g_wpH);
    cudaGetSymbolAddress((void**)&WPL, g_wpL);
    cudaGetSymbolAddress((void**)&CNT, g_cnt);

    cudaFuncSetAttribute(k_gemm_mma<0,0,1>, cudaFuncAttributeMaxDynamicSharedMemorySize, TC_SMEM);
    cudaFuncSetAttribute(k_gemm_mma<0,1,1>, cudaFuncAttributeMaxDynamicSharedMemorySize, TC_SMEM);
    cudaFuncSetAttribute(k_gemm_mma<1,1,0>, cudaFuncAttributeMaxDynamicSharedMemorySize, TC_SMEM);

    const int TB = 256;
    int gb_e   = (E + TB - 1) / TB;
    int ntiles = (n + 127) / 128;               // 128-row gemm tiles
    int gb_w   = ((n * 8) + TB - 1) / TB;       // gather blocks (8 thr/node)
    int nb     = (n + 255) / 256;               // scan1 blocks
    int gb_s3  = (n + 511) / 512;               // scan3 blocks (512 thr)

    // ---- fork: side stream runs prep + GEMM1 (independent of CSR) ----
    cudaEventRecord(g_evF, 0);
    cudaStreamWaitEvent(g_s2, g_evF, 0);

    k_prep<<<7, TB, 0, g_s2>>>(W1, W2, pW2, W3, pW1,
                               b1, bn1g, bn1b, bn1m, bn1v,
                               b2, bn2g, bn2b, bn2m, bn2v,
                               b3, pb1);
    k_gemm_mma<0,0,1><<<ntiles, TB, TC_SMEM, g_s2>>>(x, WPH + 0, WPL + 0,
                                                     nullptr, Hh, n);
    cudaEventRecord(g_evJ, g_s2);

    // ---- main stream: CSR build ----
    cudaMemsetAsync(CNT, 0, (size_t)n * sizeof(int));
    k_detect<<<1, 32>>>((const unsigned int*)ei);
    k_count<<<gb_e, TB>>>(ei, E);
    k_scan1<<<nb, 256>>>(n);
    k_scan3<<<gb_s3, 512>>>(n, nb);
    k_fill<<<gb_e, TB>>>(ei, E);

    // ---- join: gather-1 needs Hh (side) + CSR + BN consts ----
    cudaStreamWaitEvent(0, g_evJ, 0);

    // layer 1 aggregation + BN1/ReLU (fp16 in/out)
    k_gather<1><<<gb_w, TB>>>(Hh, Gh, n);

    // layer 2
    k_gemm_mma<0,1,1><<<ntiles, TB, TC_SMEM>>>(Gh, WPH + 576, WPL + 576, nullptr, Hh, n);
    k_gather<2><<<gb_w, TB>>>(Hh, Gh, n);

    // layer 3 + predictor-GEMM1 merged: Gh = tanh(agg(Gh @ Wm) + fb)
    k_gemm_mma<0,1,1><<<ntiles, TB, TC_SMEM>>>(Gh, WPH + 1152, WPL + 1152, nullptr, Hh, n);
    k_gather<3><<<gb_w, TB>>>(Hh, Gh, n);

    // predictor output GEMM (fp16 in, fp32 out, +bias)
    k_gemm_mma<1,1,0><<<ntiles, TB, TC_SMEM>>>(Gh, WPH + 1728, WPL + 1728, pb2, out, n);
}